// round 1
// baseline (speedup 1.0000x reference)
#include <cuda_runtime.h>
#include <cuda_bf16.h>
#include <math.h>

// Problem constants
#define Bc 4
#define Sc 2048
#define Dc 768
#define Hc 12
#define DHc 64
#define Fc 3072
#define Lc 4
#define Mc (Bc*Sc)   // 8192 rows

// ---------------------------------------------------------------------------
// Scratch (device globals; no allocation allowed)
// ---------------------------------------------------------------------------
__device__ float g_x[(size_t)Mc*Dc];     // running activation
__device__ float g_q[(size_t)Mc*Dc];
__device__ float g_k[(size_t)Mc*Dc];
__device__ float g_v[(size_t)Mc*Dc];
__device__ float g_ao[(size_t)Mc*Dc];    // attention (av) output, [B,S,D]
__device__ float g_proj[(size_t)Mc*Dc];  // av @ Wo + bo
__device__ float g_h[(size_t)Mc*Dc];     // post-LN1
__device__ float g_f1[(size_t)Mc*Fc];    // gelu(h@W1+b1)
__device__ float g_f2[(size_t)Mc*Dc];    // f1@W2+b2

// ---------------------------------------------------------------------------
// Tiled fp32 GEMM: C[M,N] = A[M,K] @ W[K,N] (+bias) (+exact GELU)
// BM=BN=128, BK=8, 256 threads, 8x8 per thread.
// Requires M%128==0, N%128==0, K%8==0 (all satisfied here).
// ---------------------------------------------------------------------------
__global__ void __launch_bounds__(256) gemm_tiled(
    const float* __restrict__ A, const float* __restrict__ W,
    const float* __restrict__ bias, float* __restrict__ C,
    int M, int N, int K, int epi)
{
    __shared__ float As[8][132];
    __shared__ float Bs[8][132];

    const int tid = threadIdx.x;
    const int tx = tid & 15;         // 0..15 (col group)
    const int ty = tid >> 4;         // 0..15 (row group)
    const int m0 = blockIdx.y * 128;
    const int n0 = blockIdx.x * 128;

    // A-load mapping: 128 rows x 8 cols; each thread: one float4
    const int ar = tid >> 1;             // 0..127
    const int ak = (tid & 1) * 4;        // 0 or 4
    // B-load mapping: 8 rows x 128 cols; each thread: one float4
    const int bk = tid >> 5;             // 0..7
    const int bn = (tid & 31) * 4;       // 0..124

    const float* Aptr = A + (size_t)(m0 + ar) * K + ak;
    const float* Bptr = W + (size_t)bk * N + n0 + bn;

    float acc[8][8];
    #pragma unroll
    for (int i = 0; i < 8; i++)
        #pragma unroll
        for (int j = 0; j < 8; j++) acc[i][j] = 0.f;

    for (int k0 = 0; k0 < K; k0 += 8) {
        float4 av = *(const float4*)(Aptr + k0);
        float4 bv = *(const float4*)(Bptr + (size_t)k0 * N);
        __syncthreads();
        As[ak+0][ar] = av.x; As[ak+1][ar] = av.y;
        As[ak+2][ar] = av.z; As[ak+3][ar] = av.w;
        *(float4*)&Bs[bk][bn] = bv;
        __syncthreads();
        #pragma unroll
        for (int kk = 0; kk < 8; kk++) {
            float4 a0 = *(const float4*)&As[kk][ty*8];
            float4 a1 = *(const float4*)&As[kk][ty*8+4];
            float4 b0 = *(const float4*)&Bs[kk][tx*8];
            float4 b1 = *(const float4*)&Bs[kk][tx*8+4];
            float a[8] = {a0.x,a0.y,a0.z,a0.w,a1.x,a1.y,a1.z,a1.w};
            float b[8] = {b0.x,b0.y,b0.z,b0.w,b1.x,b1.y,b1.z,b1.w};
            #pragma unroll
            for (int i = 0; i < 8; i++)
                #pragma unroll
                for (int j = 0; j < 8; j++)
                    acc[i][j] = fmaf(a[i], b[j], acc[i][j]);
        }
    }

    // Epilogue
    float bvreg[8];
    #pragma unroll
    for (int j = 0; j < 8; j++)
        bvreg[j] = bias ? bias[n0 + tx*8 + j] : 0.f;

    #pragma unroll
    for (int i = 0; i < 8; i++) {
        float* crow = C + (size_t)(m0 + ty*8 + i) * N + n0 + tx*8;
        float out[8];
        #pragma unroll
        for (int j = 0; j < 8; j++) {
            float val = acc[i][j] + bvreg[j];
            if (epi == 1) {  // exact GELU
                val = 0.5f * val * (1.0f + erff(val * 0.70710678118654752f));
            }
            out[j] = val;
        }
        *(float4*)(crow)     = *(float4*)&out[0];
        *(float4*)(crow + 4) = *(float4*)&out[4];
    }
}

// ---------------------------------------------------------------------------
// Flash attention (causal), fp32. One block = 64 query rows of one (b,h).
// 256 threads; score/prob tile staged in smem; online softmax.
// q,k,v,o are [B,S,D] with head h occupying cols [h*64, h*64+64).
// ---------------------------------------------------------------------------
#define FA_PAD 68
#define FA_SMEM ((4*64*FA_PAD + 3*64) * 4)

__global__ void __launch_bounds__(256) flash_attn(
    const float* __restrict__ q, const float* __restrict__ k,
    const float* __restrict__ v, float* __restrict__ o)
{
    extern __shared__ float sm[];
    float* Qs    = sm;                    // 64 x FA_PAD
    float* Ks    = Qs + 64*FA_PAD;
    float* Vs    = Ks + 64*FA_PAD;
    float* Ss    = Vs + 64*FA_PAD;
    float* row_m = Ss + 64*FA_PAD;        // 64
    float* row_l = row_m + 64;
    float* row_a = row_l + 64;

    const int tid = threadIdx.x;
    const int bh  = blockIdx.y;             // b*H + h
    const int b   = bh / Hc;
    const int h   = bh - b * Hc;
    const int qt  = blockIdx.x;
    const int q0  = qt * 64;

    const size_t base = (size_t)b * Sc * Dc + (size_t)h * DHc;

    // Load Q tile
    {
        const int d = tid & 63, r = tid >> 6;   // r: 0..3
        #pragma unroll
        for (int i = 0; i < 16; i++) {
            int rr = r + i*4;
            Qs[rr*FA_PAD + d] = q[base + (size_t)(q0 + rr)*Dc + d];
        }
    }
    if (tid < 64) { row_m[tid] = -1e30f; row_l[tid] = 0.f; }

    float acc[4][4];
    #pragma unroll
    for (int i = 0; i < 4; i++)
        #pragma unroll
        for (int j = 0; j < 4; j++) acc[i][j] = 0.f;

    const int tr = (tid >> 4) * 4;   // query-row offset within tile
    const int tc = (tid & 15) * 4;   // key-col / out-dim offset

    for (int kt = 0; kt <= qt; kt++) {
        const int k0 = kt * 64;
        __syncthreads();   // previous phase done with Ks/Vs/Ss
        {
            const int d = tid & 63, r = tid >> 6;
            #pragma unroll
            for (int i = 0; i < 16; i++) {
                int rr = r + i*4;
                size_t gidx = base + (size_t)(k0 + rr)*Dc + d;
                Ks[rr*FA_PAD + d] = k[gidx];
                Vs[rr*FA_PAD + d] = v[gidx];
            }
        }
        __syncthreads();

        // Phase A: S = (Q @ K^T) * 1/sqrt(64), causal mask on diagonal tile
        float s[4][4];
        #pragma unroll
        for (int i = 0; i < 4; i++)
            #pragma unroll
            for (int j = 0; j < 4; j++) s[i][j] = 0.f;
        #pragma unroll 8
        for (int d = 0; d < 64; d++) {
            float a0[4], b0[4];
            #pragma unroll
            for (int i = 0; i < 4; i++) a0[i] = Qs[(tr+i)*FA_PAD + d];
            #pragma unroll
            for (int j = 0; j < 4; j++) b0[j] = Ks[(tc+j)*FA_PAD + d];
            #pragma unroll
            for (int i = 0; i < 4; i++)
                #pragma unroll
                for (int j = 0; j < 4; j++)
                    s[i][j] = fmaf(a0[i], b0[j], s[i][j]);
        }
        const bool diag = (kt == qt);
        #pragma unroll
        for (int i = 0; i < 4; i++)
            #pragma unroll
            for (int j = 0; j < 4; j++) {
                float val = s[i][j] * 0.125f;
                if (diag && (tc + j) > (tr + i)) val = -1e30f;
                Ss[(tr+i)*FA_PAD + tc + j] = val;
            }
        __syncthreads();

        // Phase B: online-softmax row update (4 threads per row)
        {
            const int row = tid >> 2, part = tid & 3;
            float sv[16];
            float mloc = -1e30f;
            #pragma unroll
            for (int j = 0; j < 16; j++) {
                sv[j] = Ss[row*FA_PAD + part*16 + j];
                mloc = fmaxf(mloc, sv[j]);
            }
            mloc = fmaxf(mloc, __shfl_xor_sync(0xFFFFFFFFu, mloc, 1));
            mloc = fmaxf(mloc, __shfl_xor_sync(0xFFFFFFFFu, mloc, 2));
            const float mold = row_m[row];
            const float mnew = fmaxf(mold, mloc);
            float lsum = 0.f;
            #pragma unroll
            for (int j = 0; j < 16; j++) {
                float p = __expf(sv[j] - mnew);
                Ss[row*FA_PAD + part*16 + j] = p;
                lsum += p;
            }
            lsum += __shfl_xor_sync(0xFFFFFFFFu, lsum, 1);
            lsum += __shfl_xor_sync(0xFFFFFFFFu, lsum, 2);
            if (part == 0) {
                const float alpha = __expf(mold - mnew);
                row_a[row] = alpha;
                row_l[row] = row_l[row] * alpha + lsum;
                row_m[row] = mnew;
            }
        }
        __syncthreads();

        // Phase C: O = alpha*O + P @ V
        {
            float al[4];
            #pragma unroll
            for (int i = 0; i < 4; i++) al[i] = row_a[tr + i];
            #pragma unroll
            for (int i = 0; i < 4; i++)
                #pragma unroll
                for (int j = 0; j < 4; j++) acc[i][j] *= al[i];
            #pragma unroll 8
            for (int kk = 0; kk < 64; kk++) {
                float p0[4], v0[4];
                #pragma unroll
                for (int i = 0; i < 4; i++) p0[i] = Ss[(tr+i)*FA_PAD + kk];
                #pragma unroll
                for (int j = 0; j < 4; j++) v0[j] = Vs[kk*FA_PAD + tc + j];
                #pragma unroll
                for (int i = 0; i < 4; i++)
                    #pragma unroll
                    for (int j = 0; j < 4; j++)
                        acc[i][j] = fmaf(p0[i], v0[j], acc[i][j]);
            }
        }
    }

    __syncthreads();
    float linv[4];
    #pragma unroll
    for (int i = 0; i < 4; i++) linv[i] = 1.0f / row_l[tr + i];
    #pragma unroll
    for (int i = 0; i < 4; i++) {
        float* orow = o + base + (size_t)(q0 + tr + i) * Dc + tc;
        #pragma unroll
        for (int j = 0; j < 4; j++) orow[j] = acc[i][j] * linv[i];
    }
}

// ---------------------------------------------------------------------------
// out = LayerNorm(res + y) * g + b   (row length 768, one block per row)
// ---------------------------------------------------------------------------
__global__ void __launch_bounds__(256) add_ln(
    const float* __restrict__ res, const float* __restrict__ y,
    const float* __restrict__ gw, const float* __restrict__ bw,
    float* __restrict__ out)
{
    const int row = blockIdx.x;
    const float* r  = res + (size_t)row * Dc;
    const float* yy = y   + (size_t)row * Dc;
    float v[3];
    float s = 0.f, s2 = 0.f;
    #pragma unroll
    for (int qq = 0; qq < 3; qq++) {
        int idx = threadIdx.x + qq*256;
        float t = r[idx] + yy[idx];
        v[qq] = t; s += t; s2 += t*t;
    }
    #pragma unroll
    for (int off = 16; off; off >>= 1) {
        s  += __shfl_xor_sync(0xFFFFFFFFu, s,  off);
        s2 += __shfl_xor_sync(0xFFFFFFFFu, s2, off);
    }
    __shared__ float sh[2][8];
    const int w = threadIdx.x >> 5, lane = threadIdx.x & 31;
    if (lane == 0) { sh[0][w] = s; sh[1][w] = s2; }
    __syncthreads();
    float ts = 0.f, ts2 = 0.f;
    #pragma unroll
    for (int i = 0; i < 8; i++) { ts += sh[0][i]; ts2 += sh[1][i]; }
    const float mu  = ts  * (1.0f/768.0f);
    const float var = ts2 * (1.0f/768.0f) - mu*mu;
    const float rstd = rsqrtf(var + 1e-5f);
    #pragma unroll
    for (int qq = 0; qq < 3; qq++) {
        int idx = threadIdx.x + qq*256;
        out[(size_t)row*Dc + idx] = (v[qq] - mu) * rstd * gw[idx] + bw[idx];
    }
}

// ---------------------------------------------------------------------------
// Host launcher
// ---------------------------------------------------------------------------
extern "C" void kernel_launch(void* const* d_in, const int* in_sizes, int n_in,
                              void* d_out, int out_size)
{
    const float* x    = (const float*)d_in[0];
    // d_in[1] = attn_mask (bool causal) — statically known, not read
    const float* Wq   = (const float*)d_in[2];
    const float* Wk   = (const float*)d_in[3];
    const float* Wv   = (const float*)d_in[4];
    const float* Wo   = (const float*)d_in[5];
    const float* bo   = (const float*)d_in[6];
    const float* ln1g = (const float*)d_in[7];
    const float* ln1b = (const float*)d_in[8];
    const float* W1   = (const float*)d_in[9];
    const float* b1   = (const float*)d_in[10];
    const float* W2   = (const float*)d_in[11];
    const float* b2   = (const float*)d_in[12];
    const float* ln2g = (const float*)d_in[13];
    const float* ln2b = (const float*)d_in[14];

    float *gx, *gq, *gk, *gv, *gao, *gproj, *gh, *gf1, *gf2;
    cudaGetSymbolAddress((void**)&gx,    g_x);
    cudaGetSymbolAddress((void**)&gq,    g_q);
    cudaGetSymbolAddress((void**)&gk,    g_k);
    cudaGetSymbolAddress((void**)&gv,    g_v);
    cudaGetSymbolAddress((void**)&gao,   g_ao);
    cudaGetSymbolAddress((void**)&gproj, g_proj);
    cudaGetSymbolAddress((void**)&gh,    g_h);
    cudaGetSymbolAddress((void**)&gf1,   g_f1);
    cudaGetSymbolAddress((void**)&gf2,   g_f2);

    cudaFuncSetAttribute(flash_attn, cudaFuncAttributeMaxDynamicSharedMemorySize, FA_SMEM);

    cudaMemcpyAsync(gx, x, (size_t)Mc*Dc*sizeof(float), cudaMemcpyDeviceToDevice);

    const dim3 gD(Dc/128, Mc/128);   // (6, 64)
    const dim3 gF(Fc/128, Mc/128);   // (24, 64)

    for (int l = 0; l < Lc; l++) {
        const float* wq = Wq + (size_t)l*Dc*Dc;
        const float* wk = Wk + (size_t)l*Dc*Dc;
        const float* wv = Wv + (size_t)l*Dc*Dc;
        const float* wo = Wo + (size_t)l*Dc*Dc;
        const float* bol = bo + (size_t)l*Dc;
        const float* w1 = W1 + (size_t)l*Dc*Fc;
        const float* b1l = b1 + (size_t)l*Fc;
        const float* w2 = W2 + (size_t)l*Fc*Dc;
        const float* b2l = b2 + (size_t)l*Dc;

        gemm_tiled<<<gD, 256>>>(gx, wq, nullptr, gq, Mc, Dc, Dc, 0);
        gemm_tiled<<<gD, 256>>>(gx, wk, nullptr, gk, Mc, Dc, Dc, 0);
        gemm_tiled<<<gD, 256>>>(gx, wv, nullptr, gv, Mc, Dc, Dc, 0);

        flash_attn<<<dim3(Sc/64, Bc*Hc), 256, FA_SMEM>>>(gq, gk, gv, gao);

        gemm_tiled<<<gD, 256>>>(gao, wo, bol, gproj, Mc, Dc, Dc, 0);
        add_ln<<<Mc, 256>>>(gx, gproj, ln1g + (size_t)l*Dc, ln1b + (size_t)l*Dc, gh);

        gemm_tiled<<<gF, 256>>>(gh,  w1, b1l, gf1, Mc, Fc, Dc, 1);
        gemm_tiled<<<gD, 256>>>(gf1, w2, b2l, gf2, Mc, Dc, Fc, 0);
        add_ln<<<Mc, 256>>>(gh, gf2, ln2g + (size_t)l*Dc, ln2b + (size_t)l*Dc, gx);
    }

    cudaMemcpyAsync(d_out, gx, (size_t)Mc*Dc*sizeof(float), cudaMemcpyDeviceToDevice);
}

// round 7
// speedup vs baseline: 1.7700x; 1.7700x over previous
#include <cuda_runtime.h>
#include <cuda_bf16.h>
#include <math.h>
#include <stdint.h>

// Problem constants
#define Bc 4
#define Sc 2048
#define Dc 768
#define Hc 12
#define DHc 64
#define Fc 3072
#define Lc 4
#define Mc (Bc*Sc)   // 8192 rows

// ---------------------------------------------------------------------------
// Scratch (device globals; no allocation allowed)
// ---------------------------------------------------------------------------
__device__ float g_x[(size_t)Mc*Dc];
__device__ float g_q[(size_t)Mc*Dc];
__device__ float g_k[(size_t)Mc*Dc];
__device__ float g_v[(size_t)Mc*Dc];
__device__ float g_ao[(size_t)Mc*Dc];
__device__ float g_proj[(size_t)Mc*Dc];
__device__ float g_h[(size_t)Mc*Dc];
__device__ float g_f1[(size_t)Mc*Fc];
__device__ float g_f2[(size_t)Mc*Dc];

// bf16 split activations (max width F=3072)
__device__ __nv_bfloat16 g_act_hi[(size_t)Mc*Fc];
__device__ __nv_bfloat16 g_act_lo[(size_t)Mc*Fc];

// bf16 split transposed weights, all layers
#define WT_PER_LAYER ((size_t)4*Dc*Dc + 2*(size_t)Dc*Fc)
__device__ __nv_bfloat16 g_wt_hi[WT_PER_LAYER*Lc];
__device__ __nv_bfloat16 g_wt_lo[WT_PER_LAYER*Lc];

// ---------------------------------------------------------------------------
// Helpers
// ---------------------------------------------------------------------------
__device__ __forceinline__ uint32_t smem_u32(const void* p){
    uint32_t a;
    asm("{ .reg .u64 t; cvta.to.shared.u64 t, %1; cvt.u32.u64 %0, t; }":"=r"(a):"l"(p));
    return a;
}
__device__ __forceinline__ void cpasync16(uint32_t dst, const void* src){
    asm volatile("cp.async.cg.shared.global [%0], [%1], 16;" :: "r"(dst), "l"(src));
}
#define CP_COMMIT() asm volatile("cp.async.commit_group;" ::: "memory")

__device__ __forceinline__ void ldm_x4(uint32_t addr, uint32_t& r0, uint32_t& r1,
                                       uint32_t& r2, uint32_t& r3){
    asm volatile("ldmatrix.sync.aligned.m8n8.x4.shared.b16 {%0,%1,%2,%3}, [%4];"
        : "=r"(r0),"=r"(r1),"=r"(r2),"=r"(r3) : "r"(addr));
}
__device__ __forceinline__ void ldm_x2(uint32_t addr, uint32_t& r0, uint32_t& r1){
    asm volatile("ldmatrix.sync.aligned.m8n8.x2.shared.b16 {%0,%1}, [%2];"
        : "=r"(r0),"=r"(r1) : "r"(addr));
}
__device__ __forceinline__ void mma_bf16(float* c, const uint32_t* a, const uint32_t* b){
    asm volatile("mma.sync.aligned.m16n8k16.row.col.f32.bf16.bf16.f32 "
        "{%0,%1,%2,%3}, {%4,%5,%6,%7}, {%8,%9}, {%0,%1,%2,%3};"
        : "+f"(c[0]),"+f"(c[1]),"+f"(c[2]),"+f"(c[3])
        : "r"(a[0]),"r"(a[1]),"r"(a[2]),"r"(a[3]), "r"(b[0]),"r"(b[1]));
}

// ---------------------------------------------------------------------------
// mma.sync GEMM: C[M,N] = (Ah+Al)[M,K] @ (Bh+Bl)[N,K]^T  (3-term bf16 split)
// CTA tile 128x128, BK=32, 8 warps (2x4), warp tile 64x32.
// Smem: 2 stages x 4 tiles x (128 rows x 80B padded). ldmatrix + cp.async.
// ---------------------------------------------------------------------------
#define T_STRIDE 80              // bytes per padded row (32 bf16 data + 8 pad)
#define TILE_B   (128*T_STRIDE)  // 10240
#define STAGE_B  (4*TILE_B)      // 40960
#define GSM_TOTAL (2*STAGE_B)    // 81920

__global__ void __launch_bounds__(256, 1) gemm_tc(
    const __nv_bfloat16* __restrict__ Ah, const __nv_bfloat16* __restrict__ Al,
    const __nv_bfloat16* __restrict__ Bh, const __nv_bfloat16* __restrict__ Bl,
    const float* __restrict__ bias, float* __restrict__ C,
    int M, int N, int K, int epi)
{
    extern __shared__ char smem[];
    const uint32_t sbase = smem_u32(smem);
    const int tid = threadIdx.x;
    const int wid = tid >> 5, lane = tid & 31;
    const int warpM = wid >> 2, warpN = wid & 3;     // 2 x 4
    const int m0 = blockIdx.y * 128, n0 = blockIdx.x * 128;

    const __nv_bfloat16* srcs[4] = {Ah, Al, Bh, Bl};
    const int rowbase[4] = {m0, m0, n0, n0};

    // loader: 4 tiles x 128 rows x 4 x 16B segs = 2048 cp.async / 256 thr = 8 each
    auto load_chunk = [&](int c, int s){
        const int k0 = c * 32;
        #pragma unroll
        for (int i = 0; i < 8; i++){
            int idx = tid + i*256;               // 0..2047
            int seg  = idx & 3;
            int row  = (idx >> 2) & 127;
            int t    = idx >> 9;                 // 0..3
            uint32_t dst = sbase + s*STAGE_B + t*TILE_B + row*T_STRIDE + seg*16;
            const char* src = (const char*)(srcs[t] + (size_t)(rowbase[t] + row)*K + k0) + seg*16;
            cpasync16(dst, src);
        }
        CP_COMMIT();
    };

    float acc[4][4][4];
    #pragma unroll
    for (int i = 0; i < 4; i++)
        #pragma unroll
        for (int j = 0; j < 4; j++)
            #pragma unroll
            for (int r = 0; r < 4; r++) acc[i][j][r] = 0.f;

    const int NC = K / 32;
    load_chunk(0, 0);

    // precomputed intra-warp ldmatrix address offsets
    const uint32_t aoff = (uint32_t)(lane & 15) * T_STRIDE + (uint32_t)(lane >> 4) * 16;
    const uint32_t boff = (uint32_t)(lane & 7)  * T_STRIDE + (uint32_t)((lane >> 3) & 1) * 16;

    for (int c = 0; c < NC; c++){
        const int s = c & 1;
        if (c + 1 < NC){ load_chunk(c + 1, s ^ 1); }
        if (c + 1 < NC) asm volatile("cp.async.wait_group 1;" ::: "memory");
        else            asm volatile("cp.async.wait_group 0;" ::: "memory");
        __syncthreads();

        const uint32_t st  = sbase + s*STAGE_B;
        const uint32_t A_h = st,            A_l = st + TILE_B;
        const uint32_t B_h = st + 2*TILE_B, B_l = st + 3*TILE_B;

        #pragma unroll
        for (int ks = 0; ks < 2; ks++){
            uint32_t ah[4][4], al[4][4], bh[4][2], bl[4][2];
            #pragma unroll
            for (int i = 0; i < 4; i++){
                uint32_t ra = (uint32_t)(warpM*64 + i*16) * T_STRIDE + (uint32_t)(ks*32) + aoff;
                ldm_x4(A_h + ra, ah[i][0], ah[i][1], ah[i][2], ah[i][3]);
                ldm_x4(A_l + ra, al[i][0], al[i][1], al[i][2], al[i][3]);
            }
            #pragma unroll
            for (int j = 0; j < 4; j++){
                uint32_t rb = (uint32_t)(warpN*32 + j*8) * T_STRIDE + (uint32_t)(ks*32) + boff;
                ldm_x2(B_h + rb, bh[j][0], bh[j][1]);
                ldm_x2(B_l + rb, bl[j][0], bl[j][1]);
            }
            #pragma unroll
            for (int i = 0; i < 4; i++)
                #pragma unroll
                for (int j = 0; j < 4; j++){
                    mma_bf16(acc[i][j], ah[i], bh[j]);
                    mma_bf16(acc[i][j], ah[i], bl[j]);
                    mma_bf16(acc[i][j], al[i], bh[j]);
                }
        }
        __syncthreads();
    }

    // epilogue: thread holds (gid, tig): rows gid/gid+8, cols 2*tig..
    const int gid = lane >> 2, tig = lane & 3;
    #pragma unroll
    for (int i = 0; i < 4; i++){
        #pragma unroll
        for (int j = 0; j < 4; j++){
            const int col = n0 + warpN*32 + j*8 + tig*2;
            float b0 = bias ? bias[col]     : 0.f;
            float b1 = bias ? bias[col + 1] : 0.f;
            #pragma unroll
            for (int half = 0; half < 2; half++){
                const int row = m0 + warpM*64 + i*16 + gid + half*8;
                float v0 = acc[i][j][half*2 + 0] + b0;
                float v1 = acc[i][j][half*2 + 1] + b1;
                if (epi){
                    v0 = 0.5f * v0 * (1.0f + erff(v0 * 0.70710678118654752f));
                    v1 = 0.5f * v1 * (1.0f + erff(v1 * 0.70710678118654752f));
                }
                float2 o = make_float2(v0, v1);
                *(float2*)(C + (size_t)row * N + col) = o;
            }
        }
    }
}

// ---------------------------------------------------------------------------
// Weight transpose + bf16 split:  W[K,N] fp32  ->  out_hi/lo[N,K] bf16
// ---------------------------------------------------------------------------
__global__ void __launch_bounds__(256) transpose_split(
    const float* __restrict__ W, int K, int N,
    __nv_bfloat16* __restrict__ oh, __nv_bfloat16* __restrict__ ol)
{
    __shared__ float t[32][33];
    const int kb = blockIdx.y*32, nb = blockIdx.x*32;
    const int x = threadIdx.x & 31, y = (threadIdx.x >> 5) * 4;
    #pragma unroll
    for (int i = 0; i < 4; i++)
        t[y+i][x] = W[(size_t)(kb + y + i)*N + nb + x];
    __syncthreads();
    #pragma unroll
    for (int i = 0; i < 4; i++){
        float v = t[x][y+i];
        __nv_bfloat16 h = __float2bfloat16(v);
        float lo = v - __bfloat162float(h);
        oh[(size_t)(nb + y + i)*K + kb + x] = h;
        ol[(size_t)(nb + y + i)*K + kb + x] = __float2bfloat16(lo);
    }
}

// ---------------------------------------------------------------------------
// Activation bf16 split (elementwise)
// ---------------------------------------------------------------------------
__global__ void __launch_bounds__(256) split_act(
    const float* __restrict__ in, __nv_bfloat16* __restrict__ oh,
    __nv_bfloat16* __restrict__ ol, int n)
{
    int i = blockIdx.x * 1024 + threadIdx.x * 4;
    if (i >= n) return;
    float4 v = *(const float4*)(in + i);
    float vv[4] = {v.x, v.y, v.z, v.w};
    __nv_bfloat16 h[4], l[4];
    #pragma unroll
    for (int j = 0; j < 4; j++){
        h[j] = __float2bfloat16(vv[j]);
        l[j] = __float2bfloat16(vv[j] - __bfloat162float(h[j]));
    }
    *(uint2*)(oh + i) = *(uint2*)h;
    *(uint2*)(ol + i) = *(uint2*)l;
}

// ---------------------------------------------------------------------------
// Flash attention (causal), fp32 — unchanged
// ---------------------------------------------------------------------------
#define FA_PAD 68
#define FA_SMEM ((4*64*FA_PAD + 3*64) * 4)

__global__ void __launch_bounds__(256) flash_attn(
    const float* __restrict__ q, const float* __restrict__ k,
    const float* __restrict__ v, float* __restrict__ o)
{
    extern __shared__ float sm[];
    float* Qs    = sm;
    float* Ks    = Qs + 64*FA_PAD;
    float* Vs    = Ks + 64*FA_PAD;
    float* Ss    = Vs + 64*FA_PAD;
    float* row_m = Ss + 64*FA_PAD;
    float* row_l = row_m + 64;
    float* row_a = row_l + 64;

    const int tid = threadIdx.x;
    const int bh  = blockIdx.y;
    const int b   = bh / Hc;
    const int h   = bh - b * Hc;
    const int qt  = blockIdx.x;
    const int q0  = qt * 64;

    const size_t base = (size_t)b * Sc * Dc + (size_t)h * DHc;

    {
        const int d = tid & 63, r = tid >> 6;
        #pragma unroll
        for (int i = 0; i < 16; i++) {
            int rr = r + i*4;
            Qs[rr*FA_PAD + d] = q[base + (size_t)(q0 + rr)*Dc + d];
        }
    }
    if (tid < 64) { row_m[tid] = -1e30f; row_l[tid] = 0.f; }

    float acc[4][4];
    #pragma unroll
    for (int i = 0; i < 4; i++)
        #pragma unroll
        for (int j = 0; j < 4; j++) acc[i][j] = 0.f;

    const int tr = (tid >> 4) * 4;
    const int tc = (tid & 15) * 4;

    for (int kt = 0; kt <= qt; kt++) {
        const int k0 = kt * 64;
        __syncthreads();
        {
            const int d = tid & 63, r = tid >> 6;
            #pragma unroll
            for (int i = 0; i < 16; i++) {
                int rr = r + i*4;
                size_t gidx = base + (size_t)(k0 + rr)*Dc + d;
                Ks[rr*FA_PAD + d] = k[gidx];
                Vs[rr*FA_PAD + d] = v[gidx];
            }
        }
        __syncthreads();

        float s[4][4];
        #pragma unroll
        for (int i = 0; i < 4; i++)
            #pragma unroll
            for (int j = 0; j < 4; j++) s[i][j] = 0.f;
        #pragma unroll 8
        for (int d = 0; d < 64; d++) {
            float a0[4], b0[4];
            #pragma unroll
            for (int i = 0; i < 4; i++) a0[i] = Qs[(tr+i)*FA_PAD + d];
            #pragma unroll
            for (int j = 0; j < 4; j++) b0[j] = Ks[(tc+j)*FA_PAD + d];
            #pragma unroll
            for (int i = 0; i < 4; i++)
                #pragma unroll
                for (int j = 0; j < 4; j++)
                    s[i][j] = fmaf(a0[i], b0[j], s[i][j]);
        }
        const bool diag = (kt == qt);
        #pragma unroll
        for (int i = 0; i < 4; i++)
            #pragma unroll
            for (int j = 0; j < 4; j++) {
                float val = s[i][j] * 0.125f;
                if (diag && (tc + j) > (tr + i)) val = -1e30f;
                Ss[(tr+i)*FA_PAD + tc + j] = val;
            }
        __syncthreads();

        {
            const int row = tid >> 2, part = tid & 3;
            float sv[16];
            float mloc = -1e30f;
            #pragma unroll
            for (int j = 0; j < 16; j++) {
                sv[j] = Ss[row*FA_PAD + part*16 + j];
                mloc = fmaxf(mloc, sv[j]);
            }
            mloc = fmaxf(mloc, __shfl_xor_sync(0xFFFFFFFFu, mloc, 1));
            mloc = fmaxf(mloc, __shfl_xor_sync(0xFFFFFFFFu, mloc, 2));
            const float mold = row_m[row];
            const float mnew = fmaxf(mold, mloc);
            float lsum = 0.f;
            #pragma unroll
            for (int j = 0; j < 16; j++) {
                float p = __expf(sv[j] - mnew);
                Ss[row*FA_PAD + part*16 + j] = p;
                lsum += p;
            }
            lsum += __shfl_xor_sync(0xFFFFFFFFu, lsum, 1);
            lsum += __shfl_xor_sync(0xFFFFFFFFu, lsum, 2);
            if (part == 0) {
                const float alpha = __expf(mold - mnew);
                row_a[row] = alpha;
                row_l[row] = row_l[row] * alpha + lsum;
                row_m[row] = mnew;
            }
        }
        __syncthreads();

        {
            float al[4];
            #pragma unroll
            for (int i = 0; i < 4; i++) al[i] = row_a[tr + i];
            #pragma unroll
            for (int i = 0; i < 4; i++)
                #pragma unroll
                for (int j = 0; j < 4; j++) acc[i][j] *= al[i];
            #pragma unroll 8
            for (int kk = 0; kk < 64; kk++) {
                float p0[4], v0[4];
                #pragma unroll
                for (int i = 0; i < 4; i++) p0[i] = Ss[(tr+i)*FA_PAD + kk];
                #pragma unroll
                for (int j = 0; j < 4; j++) v0[j] = Vs[kk*FA_PAD + tc + j];
                #pragma unroll
                for (int i = 0; i < 4; i++)
                    #pragma unroll
                    for (int j = 0; j < 4; j++)
                        acc[i][j] = fmaf(p0[i], v0[j], acc[i][j]);
            }
        }
    }

    __syncthreads();
    float linv[4];
    #pragma unroll
    for (int i = 0; i < 4; i++) linv[i] = 1.0f / row_l[tr + i];
    #pragma unroll
    for (int i = 0; i < 4; i++) {
        float* orow = o + base + (size_t)(q0 + tr + i) * Dc + tc;
        #pragma unroll
        for (int j = 0; j < 4; j++) orow[j] = acc[i][j] * linv[i];
    }
}

// ---------------------------------------------------------------------------
// out = LayerNorm(res + y) * g + b   (row length 768)
// ---------------------------------------------------------------------------
__global__ void __launch_bounds__(256) add_ln(
    const float* __restrict__ res, const float* __restrict__ y,
    const float* __restrict__ gw, const float* __restrict__ bw,
    float* __restrict__ out)
{
    const int row = blockIdx.x;
    const float* r  = res + (size_t)row * Dc;
    const float* yy = y   + (size_t)row * Dc;
    float v[3];
    float s = 0.f, s2 = 0.f;
    #pragma unroll
    for (int qq = 0; qq < 3; qq++) {
        int idx = threadIdx.x + qq*256;
        float t = r[idx] + yy[idx];
        v[qq] = t; s += t; s2 += t*t;
    }
    #pragma unroll
    for (int off = 16; off; off >>= 1) {
        s  += __shfl_xor_sync(0xFFFFFFFFu, s,  off);
        s2 += __shfl_xor_sync(0xFFFFFFFFu, s2, off);
    }
    __shared__ float sh[2][8];
    const int w = threadIdx.x >> 5, lane = threadIdx.x & 31;
    if (lane == 0) { sh[0][w] = s; sh[1][w] = s2; }
    __syncthreads();
    float ts = 0.f, ts2 = 0.f;
    #pragma unroll
    for (int i = 0; i < 8; i++) { ts += sh[0][i]; ts2 += sh[1][i]; }
    const float mu  = ts  * (1.0f/768.0f);
    const float var = ts2 * (1.0f/768.0f) - mu*mu;
    const float rstd = rsqrtf(var + 1e-5f);
    #pragma unroll
    for (int qq = 0; qq < 3; qq++) {
        int idx = threadIdx.x + qq*256;
        out[(size_t)row*Dc + idx] = (v[qq] - mu) * rstd * gw[idx] + bw[idx];
    }
}

// ---------------------------------------------------------------------------
// Host launcher
// ---------------------------------------------------------------------------
extern "C" void kernel_launch(void* const* d_in, const int* in_sizes, int n_in,
                              void* d_out, int out_size)
{
    const float* x    = (const float*)d_in[0];
    const float* Wq   = (const float*)d_in[2];
    const float* Wk   = (const float*)d_in[3];
    const float* Wv   = (const float*)d_in[4];
    const float* Wo   = (const float*)d_in[5];
    const float* bo   = (const float*)d_in[6];
    const float* ln1g = (const float*)d_in[7];
    const float* ln1b = (const float*)d_in[8];
    const float* W1   = (const float*)d_in[9];
    const float* b1   = (const float*)d_in[10];
    const float* W2   = (const float*)d_in[11];
    const float* b2   = (const float*)d_in[12];
    const float* ln2g = (const float*)d_in[13];
    const float* ln2b = (const float*)d_in[14];

    float *gx, *gq, *gk, *gv, *gao, *gproj, *gh, *gf1, *gf2;
    __nv_bfloat16 *ah, *al, *wh, *wl;
    cudaGetSymbolAddress((void**)&gx,    g_x);
    cudaGetSymbolAddress((void**)&gq,    g_q);
    cudaGetSymbolAddress((void**)&gk,    g_k);
    cudaGetSymbolAddress((void**)&gv,    g_v);
    cudaGetSymbolAddress((void**)&gao,   g_ao);
    cudaGetSymbolAddress((void**)&gproj, g_proj);
    cudaGetSymbolAddress((void**)&gh,    g_h);
    cudaGetSymbolAddress((void**)&gf1,   g_f1);
    cudaGetSymbolAddress((void**)&gf2,   g_f2);
    cudaGetSymbolAddress((void**)&ah,    g_act_hi);
    cudaGetSymbolAddress((void**)&al,    g_act_lo);
    cudaGetSymbolAddress((void**)&wh,    g_wt_hi);
    cudaGetSymbolAddress((void**)&wl,    g_wt_lo);

    cudaFuncSetAttribute(flash_attn, cudaFuncAttributeMaxDynamicSharedMemorySize, FA_SMEM);
    cudaFuncSetAttribute(gemm_tc,    cudaFuncAttributeMaxDynamicSharedMemorySize, GSM_TOTAL);

    const size_t DD = (size_t)Dc*Dc, DF = (size_t)Dc*Fc;

    // ---- weight prep: transpose + split all layers
    for (int l = 0; l < Lc; l++){
        size_t wb = (size_t)l * WT_PER_LAYER;
        transpose_split<<<dim3(Dc/32, Dc/32), 256>>>(Wq + l*DD, Dc, Dc, wh + wb,        wl + wb);
        transpose_split<<<dim3(Dc/32, Dc/32), 256>>>(Wk + l*DD, Dc, Dc, wh + wb + DD,   wl + wb + DD);
        transpose_split<<<dim3(Dc/32, Dc/32), 256>>>(Wv + l*DD, Dc, Dc, wh + wb + 2*DD, wl + wb + 2*DD);
        transpose_split<<<dim3(Dc/32, Dc/32), 256>>>(Wo + l*DD, Dc, Dc, wh + wb + 3*DD, wl + wb + 3*DD);
        transpose_split<<<dim3(Fc/32, Dc/32), 256>>>(W1 + l*DF, Dc, Fc, wh + wb + 4*DD, wl + wb + 4*DD);
        transpose_split<<<dim3(Dc/32, Fc/32), 256>>>(W2 + l*DF, Fc, Dc, wh + wb + 4*DD + DF, wl + wb + 4*DD + DF);
    }

    cudaMemcpyAsync(gx, x, (size_t)Mc*Dc*sizeof(float), cudaMemcpyDeviceToDevice);

    const dim3 gD(Dc/128, Mc/128);   // (6, 64)
    const dim3 gF(Fc/128, Mc/128);   // (24, 64)
    const int nMD = Mc*Dc, nMF = Mc*Fc;

    for (int l = 0; l < Lc; l++){
        size_t wb = (size_t)l * WT_PER_LAYER;
        const __nv_bfloat16 *qh = wh+wb,        *ql = wl+wb;
        const __nv_bfloat16 *kh = wh+wb+DD,     *kl = wl+wb+DD;
        const __nv_bfloat16 *vh = wh+wb+2*DD,   *vl = wl+wb+2*DD;
        const __nv_bfloat16 *oh = wh+wb+3*DD,   *ol = wl+wb+3*DD;
        const __nv_bfloat16 *w1h= wh+wb+4*DD,   *w1l= wl+wb+4*DD;
        const __nv_bfloat16 *w2h= wh+wb+4*DD+DF,*w2l= wl+wb+4*DD+DF;

        split_act<<<nMD/1024, 256>>>(gx, ah, al, nMD);
        gemm_tc<<<gD, 256, GSM_TOTAL>>>(ah, al, qh, ql, nullptr, gq, Mc, Dc, Dc, 0);
        gemm_tc<<<gD, 256, GSM_TOTAL>>>(ah, al, kh, kl, nullptr, gk, Mc, Dc, Dc, 0);
        gemm_tc<<<gD, 256, GSM_TOTAL>>>(ah, al, vh, vl, nullptr, gv, Mc, Dc, Dc, 0);

        flash_attn<<<dim3(Sc/64, Bc*Hc), 256, FA_SMEM>>>(gq, gk, gv, gao);

        split_act<<<nMD/1024, 256>>>(gao, ah, al, nMD);
        gemm_tc<<<gD, 256, GSM_TOTAL>>>(ah, al, oh, ol, bo + (size_t)l*Dc, gproj, Mc, Dc, Dc, 0);
        add_ln<<<Mc, 256>>>(gx, gproj, ln1g + (size_t)l*Dc, ln1b + (size_t)l*Dc, gh);

        split_act<<<nMD/1024, 256>>>(gh, ah, al, nMD);
        gemm_tc<<<gF, 256, GSM_TOTAL>>>(ah, al, w1h, w1l, b1 + (size_t)l*Fc, gf1, Mc, Fc, Dc, 1);
        split_act<<<nMF/1024, 256>>>(gf1, ah, al, nMF);
        gemm_tc<<<gD, 256, GSM_TOTAL>>>(ah, al, w2h, w2l, b2 + (size_t)l*Dc, gf2, Mc, Dc, Fc, 0);
        add_ln<<<Mc, 256>>>(gh, gf2, ln2g + (size_t)l*Dc, ln2b + (size_t)l*Dc, gx);
    }

    cudaMemcpyAsync(d_out, gx, (size_t)Mc*Dc*sizeof(float), cudaMemcpyDeviceToDevice);
}

// round 8
// speedup vs baseline: 3.0550x; 1.7260x over previous
#include <cuda_runtime.h>
#include <cuda_bf16.h>
#include <math.h>
#include <stdint.h>

// Problem constants
#define Bc 4
#define Sc 2048
#define Dc 768
#define Hc 12
#define DHc 64
#define Fc 3072
#define Lc 4
#define Mc (Bc*Sc)   // 8192 rows

// ---------------------------------------------------------------------------
// Scratch (device globals; no allocation allowed)
// ---------------------------------------------------------------------------
__device__ float g_x[(size_t)Mc*Dc];
__device__ float g_q[(size_t)Mc*Dc];
__device__ float g_k[(size_t)Mc*Dc];
__device__ float g_v[(size_t)Mc*Dc];
__device__ float g_ao[(size_t)Mc*Dc];
__device__ float g_proj[(size_t)Mc*Dc];
__device__ float g_h[(size_t)Mc*Dc];
__device__ float g_f1[(size_t)Mc*Fc];
__device__ float g_f2[(size_t)Mc*Dc];

// bf16 split activations (max width F=3072)
__device__ __nv_bfloat16 g_act_hi[(size_t)Mc*Fc];
__device__ __nv_bfloat16 g_act_lo[(size_t)Mc*Fc];

// bf16 split q/k/v for attention
__device__ __nv_bfloat16 g_qh[(size_t)Mc*Dc];
__device__ __nv_bfloat16 g_ql[(size_t)Mc*Dc];
__device__ __nv_bfloat16 g_kh[(size_t)Mc*Dc];
__device__ __nv_bfloat16 g_kl[(size_t)Mc*Dc];
__device__ __nv_bfloat16 g_vh[(size_t)Mc*Dc];
__device__ __nv_bfloat16 g_vl[(size_t)Mc*Dc];

// bf16 split transposed weights, all layers
#define WT_PER_LAYER ((size_t)4*Dc*Dc + 2*(size_t)Dc*Fc)
__device__ __nv_bfloat16 g_wt_hi[WT_PER_LAYER*Lc];
__device__ __nv_bfloat16 g_wt_lo[WT_PER_LAYER*Lc];

// ---------------------------------------------------------------------------
// Helpers
// ---------------------------------------------------------------------------
__device__ __forceinline__ uint32_t smem_u32(const void* p){
    uint32_t a;
    asm("{ .reg .u64 t; cvta.to.shared.u64 t, %1; cvt.u32.u64 %0, t; }":"=r"(a):"l"(p));
    return a;
}
__device__ __forceinline__ void cpasync16(uint32_t dst, const void* src){
    asm volatile("cp.async.cg.shared.global [%0], [%1], 16;" :: "r"(dst), "l"(src));
}
#define CP_COMMIT() asm volatile("cp.async.commit_group;" ::: "memory")

__device__ __forceinline__ void ldm_x4(uint32_t addr, uint32_t& r0, uint32_t& r1,
                                       uint32_t& r2, uint32_t& r3){
    asm volatile("ldmatrix.sync.aligned.m8n8.x4.shared.b16 {%0,%1,%2,%3}, [%4];"
        : "=r"(r0),"=r"(r1),"=r"(r2),"=r"(r3) : "r"(addr));
}
__device__ __forceinline__ void ldm_x2(uint32_t addr, uint32_t& r0, uint32_t& r1){
    asm volatile("ldmatrix.sync.aligned.m8n8.x2.shared.b16 {%0,%1}, [%2];"
        : "=r"(r0),"=r"(r1) : "r"(addr));
}
__device__ __forceinline__ void ldm_x4_t(uint32_t addr, uint32_t& r0, uint32_t& r1,
                                         uint32_t& r2, uint32_t& r3){
    asm volatile("ldmatrix.sync.aligned.m8n8.x4.trans.shared.b16 {%0,%1,%2,%3}, [%4];"
        : "=r"(r0),"=r"(r1),"=r"(r2),"=r"(r3) : "r"(addr));
}
__device__ __forceinline__ void mma_bf16(float* c, const uint32_t* a, const uint32_t* b){
    asm volatile("mma.sync.aligned.m16n8k16.row.col.f32.bf16.bf16.f32 "
        "{%0,%1,%2,%3}, {%4,%5,%6,%7}, {%8,%9}, {%0,%1,%2,%3};"
        : "+f"(c[0]),"+f"(c[1]),"+f"(c[2]),"+f"(c[3])
        : "r"(a[0]),"r"(a[1]),"r"(a[2]),"r"(a[3]), "r"(b[0]),"r"(b[1]));
}
__device__ __forceinline__ uint32_t pack_bf2(__nv_bfloat16 a, __nv_bfloat16 b){
    union { __nv_bfloat162 v; uint32_t u; } t;
    t.v.x = a; t.v.y = b; return t.u;
}

// ---------------------------------------------------------------------------
// mma.sync GEMM: C[M,N] = (Ah+Al)[M,K] @ (Bh+Bl)[N,K]^T  (3-term bf16 split)
// ---------------------------------------------------------------------------
#define T_STRIDE 80
#define TILE_B   (128*T_STRIDE)
#define STAGE_B  (4*TILE_B)
#define GSM_TOTAL (2*STAGE_B)

__global__ void __launch_bounds__(256, 1) gemm_tc(
    const __nv_bfloat16* __restrict__ Ah, const __nv_bfloat16* __restrict__ Al,
    const __nv_bfloat16* __restrict__ Bh, const __nv_bfloat16* __restrict__ Bl,
    const float* __restrict__ bias, float* __restrict__ C,
    int M, int N, int K, int epi)
{
    extern __shared__ char smem[];
    const uint32_t sbase = smem_u32(smem);
    const int tid = threadIdx.x;
    const int wid = tid >> 5, lane = tid & 31;
    const int warpM = wid >> 2, warpN = wid & 3;
    const int m0 = blockIdx.y * 128, n0 = blockIdx.x * 128;

    const __nv_bfloat16* srcs[4] = {Ah, Al, Bh, Bl};
    const int rowbase[4] = {m0, m0, n0, n0};

    auto load_chunk = [&](int c, int s){
        const int k0 = c * 32;
        #pragma unroll
        for (int i = 0; i < 8; i++){
            int idx = tid + i*256;
            int seg  = idx & 3;
            int row  = (idx >> 2) & 127;
            int t    = idx >> 9;
            uint32_t dst = sbase + s*STAGE_B + t*TILE_B + row*T_STRIDE + seg*16;
            const char* src = (const char*)(srcs[t] + (size_t)(rowbase[t] + row)*K + k0) + seg*16;
            cpasync16(dst, src);
        }
        CP_COMMIT();
    };

    float acc[4][4][4];
    #pragma unroll
    for (int i = 0; i < 4; i++)
        #pragma unroll
        for (int j = 0; j < 4; j++)
            #pragma unroll
            for (int r = 0; r < 4; r++) acc[i][j][r] = 0.f;

    const int NC = K / 32;
    load_chunk(0, 0);

    const uint32_t aoff = (uint32_t)(lane & 15) * T_STRIDE + (uint32_t)(lane >> 4) * 16;
    const uint32_t boff = (uint32_t)(lane & 7)  * T_STRIDE + (uint32_t)((lane >> 3) & 1) * 16;

    for (int c = 0; c < NC; c++){
        const int s = c & 1;
        if (c + 1 < NC){ load_chunk(c + 1, s ^ 1); }
        if (c + 1 < NC) asm volatile("cp.async.wait_group 1;" ::: "memory");
        else            asm volatile("cp.async.wait_group 0;" ::: "memory");
        __syncthreads();

        const uint32_t st  = sbase + s*STAGE_B;
        const uint32_t A_h = st,            A_l = st + TILE_B;
        const uint32_t B_h = st + 2*TILE_B, B_l = st + 3*TILE_B;

        #pragma unroll
        for (int ks = 0; ks < 2; ks++){
            uint32_t ah[4][4], al[4][4], bh[4][2], bl[4][2];
            #pragma unroll
            for (int i = 0; i < 4; i++){
                uint32_t ra = (uint32_t)(warpM*64 + i*16) * T_STRIDE + (uint32_t)(ks*32) + aoff;
                ldm_x4(A_h + ra, ah[i][0], ah[i][1], ah[i][2], ah[i][3]);
                ldm_x4(A_l + ra, al[i][0], al[i][1], al[i][2], al[i][3]);
            }
            #pragma unroll
            for (int j = 0; j < 4; j++){
                uint32_t rb = (uint32_t)(warpN*32 + j*8) * T_STRIDE + (uint32_t)(ks*32) + boff;
                ldm_x2(B_h + rb, bh[j][0], bh[j][1]);
                ldm_x2(B_l + rb, bl[j][0], bl[j][1]);
            }
            #pragma unroll
            for (int i = 0; i < 4; i++)
                #pragma unroll
                for (int j = 0; j < 4; j++){
                    mma_bf16(acc[i][j], ah[i], bh[j]);
                    mma_bf16(acc[i][j], ah[i], bl[j]);
                    mma_bf16(acc[i][j], al[i], bh[j]);
                }
        }
        __syncthreads();
    }

    const int gid = lane >> 2, tig = lane & 3;
    #pragma unroll
    for (int i = 0; i < 4; i++){
        #pragma unroll
        for (int j = 0; j < 4; j++){
            const int col = n0 + warpN*32 + j*8 + tig*2;
            float b0 = bias ? bias[col]     : 0.f;
            float b1 = bias ? bias[col + 1] : 0.f;
            #pragma unroll
            for (int half = 0; half < 2; half++){
                const int row = m0 + warpM*64 + i*16 + gid + half*8;
                float v0 = acc[i][j][half*2 + 0] + b0;
                float v1 = acc[i][j][half*2 + 1] + b1;
                if (epi){
                    v0 = 0.5f * v0 * (1.0f + erff(v0 * 0.70710678118654752f));
                    v1 = 0.5f * v1 * (1.0f + erff(v1 * 0.70710678118654752f));
                }
                float2 o = make_float2(v0, v1);
                *(float2*)(C + (size_t)row * N + col) = o;
            }
        }
    }
}

// ---------------------------------------------------------------------------
// Flash attention via mma.sync (causal), 3-term bf16 split everywhere.
// Block = 64 q rows of one (b,h); 128 threads = 4 warps; warp = 16 rows x 64.
// K-tile = 64; q/k/v pre-split bf16 in global; cp.async loads; 144B rows.
// ---------------------------------------------------------------------------
#define AT_STRIDE 144
#define AQ_H 0
#define AQ_L 9216
#define AK_H 18432
#define AK_L 27648
#define AV_H 36864
#define AV_L 46080
#define FA2_SMEM 55296

__global__ void __launch_bounds__(128) flash_attn_mma(
    const __nv_bfloat16* __restrict__ qh_g, const __nv_bfloat16* __restrict__ ql_g,
    const __nv_bfloat16* __restrict__ kh_g, const __nv_bfloat16* __restrict__ kl_g,
    const __nv_bfloat16* __restrict__ vh_g, const __nv_bfloat16* __restrict__ vl_g,
    float* __restrict__ o)
{
    extern __shared__ char smem[];
    const uint32_t sbase = smem_u32(smem);
    const int tid = threadIdx.x;
    const int wid = tid >> 5, lane = tid & 31;
    const int gid = lane >> 2, tig = lane & 3;
    const int bh = blockIdx.y;
    const int b = bh / Hc, h = bh - b*Hc;
    const int qt = blockIdx.x;
    const int q0 = qt * 64;
    const size_t base_e = (size_t)b * Sc * Dc + (size_t)h * DHc;

    // ---- load Q tile (both splits) via cp.async: 64 rows x 128B, 8 chunks/row
    {
        const __nv_bfloat16* qsrc[2] = {qh_g, ql_g};
        const uint32_t qdst[2] = {AQ_H, AQ_L};
        #pragma unroll
        for (int i = 0; i < 8; i++){
            int idx = tid + i*128;            // 0..1023
            int arr = idx >> 9;               // 0..1
            int rem = idx & 511;
            int row = rem >> 3, ch = rem & 7;
            const char* src = (const char*)(qsrc[arr] + base_e + (size_t)(q0 + row)*Dc) + ch*16;
            cpasync16(sbase + qdst[arr] + row*AT_STRIDE + ch*16, src);
        }
        CP_COMMIT();
    }
    asm volatile("cp.async.wait_group 0;" ::: "memory");
    __syncthreads();

    // ---- Q fragments (held in registers for the whole kernel)
    uint32_t qhf[4][4], qlf[4][4];
    {
        const uint32_t aoff = (uint32_t)(lane & 15)*AT_STRIDE + (uint32_t)(lane >> 4)*16;
        #pragma unroll
        for (int ks = 0; ks < 4; ks++){
            uint32_t ra = (uint32_t)(wid*16)*AT_STRIDE + (uint32_t)(ks*32) + aoff;
            ldm_x4(sbase + AQ_H + ra, qhf[ks][0], qhf[ks][1], qhf[ks][2], qhf[ks][3]);
            ldm_x4(sbase + AQ_L + ra, qlf[ks][0], qlf[ks][1], qlf[ks][2], qlf[ks][3]);
        }
    }

    float accO[8][4];
    #pragma unroll
    for (int j = 0; j < 8; j++)
        #pragma unroll
        for (int c = 0; c < 4; c++) accO[j][c] = 0.f;
    float m_run[2] = {-1e30f, -1e30f};
    float l_run[2] = {0.f, 0.f};

    const __nv_bfloat16* kvsrc[4] = {kh_g, kl_g, vh_g, vl_g};
    const uint32_t kvdst[4] = {AK_H, AK_L, AV_H, AV_L};

    // B-frag address patterns
    const uint32_t boff4 = (uint32_t)((lane & 7) + ((lane >> 4) << 3))*AT_STRIDE
                         + (uint32_t)((lane >> 3) & 1)*16;           // K (non-trans x4)
    const uint32_t voff4 = (uint32_t)(lane & 15)*AT_STRIDE + (uint32_t)(lane >> 4)*16; // V (trans x4)

    const int row0 = q0 + wid*16 + gid;
    const int row1 = row0 + 8;

    for (int kt = 0; kt <= qt; kt++){
        const int k0 = kt * 64;
        __syncthreads();   // previous compute done with K/V smem
        #pragma unroll
        for (int i = 0; i < 16; i++){
            int idx = tid + i*128;            // 0..2047
            int arr = idx >> 9;               // 0..3
            int rem = idx & 511;
            int row = rem >> 3, ch = rem & 7;
            const char* src = (const char*)(kvsrc[arr] + base_e + (size_t)(k0 + row)*Dc) + ch*16;
            cpasync16(sbase + kvdst[arr] + row*AT_STRIDE + ch*16, src);
        }
        CP_COMMIT();
        asm volatile("cp.async.wait_group 0;" ::: "memory");
        __syncthreads();

        // ---- S = Q K^T (3 terms)
        float accS[8][4];
        #pragma unroll
        for (int j = 0; j < 8; j++)
            #pragma unroll
            for (int c = 0; c < 4; c++) accS[j][c] = 0.f;

        #pragma unroll
        for (int ks = 0; ks < 4; ks++){
            #pragma unroll
            for (int jj = 0; jj < 4; jj++){
                uint32_t rb = (uint32_t)(jj*16)*AT_STRIDE + (uint32_t)(ks*32) + boff4;
                uint32_t bh4[4], bl4[4];
                ldm_x4(sbase + AK_H + rb, bh4[0], bh4[1], bh4[2], bh4[3]);
                ldm_x4(sbase + AK_L + rb, bl4[0], bl4[1], bl4[2], bl4[3]);
                mma_bf16(accS[2*jj],   qhf[ks], bh4 + 0);
                mma_bf16(accS[2*jj],   qhf[ks], bl4 + 0);
                mma_bf16(accS[2*jj],   qlf[ks], bh4 + 0);
                mma_bf16(accS[2*jj+1], qhf[ks], bh4 + 2);
                mma_bf16(accS[2*jj+1], qhf[ks], bl4 + 2);
                mma_bf16(accS[2*jj+1], qlf[ks], bh4 + 2);
            }
        }

        // ---- scale + causal mask (only diagonal tile)
        const bool diag = (kt == qt);
        #pragma unroll
        for (int j = 0; j < 8; j++){
            #pragma unroll
            for (int c = 0; c < 4; c++){
                float s = accS[j][c] * 0.125f;
                if (diag){
                    int col = k0 + j*8 + tig*2 + (c & 1);
                    int row = (c < 2) ? row0 : row1;
                    if (col > row) s = -1e30f;
                }
                accS[j][c] = s;
            }
        }

        // ---- online softmax (rows fully within quad)
        #pragma unroll
        for (int half = 0; half < 2; half++){
            float mloc = -1e30f;
            #pragma unroll
            for (int j = 0; j < 8; j++){
                mloc = fmaxf(mloc, accS[j][half*2]);
                mloc = fmaxf(mloc, accS[j][half*2+1]);
            }
            mloc = fmaxf(mloc, __shfl_xor_sync(0xFFFFFFFFu, mloc, 1));
            mloc = fmaxf(mloc, __shfl_xor_sync(0xFFFFFFFFu, mloc, 2));
            const float mnew = fmaxf(m_run[half], mloc);
            const float alpha = __expf(m_run[half] - mnew);
            m_run[half] = mnew;
            float psum = 0.f;
            #pragma unroll
            for (int j = 0; j < 8; j++){
                float p0 = __expf(accS[j][half*2]   - mnew);
                float p1 = __expf(accS[j][half*2+1] - mnew);
                accS[j][half*2]   = p0;
                accS[j][half*2+1] = p1;
                psum += p0 + p1;
            }
            psum += __shfl_xor_sync(0xFFFFFFFFu, psum, 1);
            psum += __shfl_xor_sync(0xFFFFFFFFu, psum, 2);
            l_run[half] = l_run[half]*alpha + psum;
            #pragma unroll
            for (int j = 0; j < 8; j++){
                accO[j][half*2]   *= alpha;
                accO[j][half*2+1] *= alpha;
            }
        }

        // ---- O += P V (3 terms); P split in-register, S-frag == A-frag layout
        #pragma unroll
        for (int ks = 0; ks < 4; ks++){
            uint32_t aPh[4], aPl[4];
            #pragma unroll
            for (int t = 0; t < 4; t++){
                const int j = 2*ks + (t >> 1);
                const int c0 = (t & 1)*2;
                float f0 = accS[j][c0], f1 = accS[j][c0+1];
                __nv_bfloat16 h0 = __float2bfloat16(f0);
                __nv_bfloat16 h1 = __float2bfloat16(f1);
                aPh[t] = pack_bf2(h0, h1);
                aPl[t] = pack_bf2(__float2bfloat16(f0 - __bfloat162float(h0)),
                                  __float2bfloat16(f1 - __bfloat162float(h1)));
            }
            // reorder to (a0,a1,a2,a3) = (j0c01, j0c23, j1c01, j1c23)
            // built order above: t0=j0c01, t1=j0c23, t2=j1c01, t3=j1c23  ✓
            #pragma unroll
            for (int jj = 0; jj < 4; jj++){
                uint32_t rv = (uint32_t)(ks*16)*AT_STRIDE + (uint32_t)(jj*32) + voff4;
                uint32_t vh4[4], vl4[4];
                ldm_x4_t(sbase + AV_H + rv, vh4[0], vh4[1], vh4[2], vh4[3]);
                ldm_x4_t(sbase + AV_L + rv, vl4[0], vl4[1], vl4[2], vl4[3]);
                mma_bf16(accO[2*jj],   aPh, vh4 + 0);
                mma_bf16(accO[2*jj],   aPh, vl4 + 0);
                mma_bf16(accO[2*jj],   aPl, vh4 + 0);
                mma_bf16(accO[2*jj+1], aPh, vh4 + 2);
                mma_bf16(accO[2*jj+1], aPh, vl4 + 2);
                mma_bf16(accO[2*jj+1], aPl, vh4 + 2);
            }
        }
    }

    // ---- write O
    const float rl0 = 1.0f / l_run[0];
    const float rl1 = 1.0f / l_run[1];
    #pragma unroll
    for (int j = 0; j < 8; j++){
        const int col = j*8 + tig*2;
        float2 o0 = make_float2(accO[j][0]*rl0, accO[j][1]*rl0);
        float2 o1 = make_float2(accO[j][2]*rl1, accO[j][3]*rl1);
        *(float2*)(o + base_e + (size_t)row0 * Dc + col) = o0;
        *(float2*)(o + base_e + (size_t)row1 * Dc + col) = o1;
    }
}

// ---------------------------------------------------------------------------
// Weight transpose + bf16 split:  W[K,N] fp32  ->  out_hi/lo[N,K] bf16
// ---------------------------------------------------------------------------
__global__ void __launch_bounds__(256) transpose_split(
    const float* __restrict__ W, int K, int N,
    __nv_bfloat16* __restrict__ oh, __nv_bfloat16* __restrict__ ol)
{
    __shared__ float t[32][33];
    const int kb = blockIdx.y*32, nb = blockIdx.x*32;
    const int x = threadIdx.x & 31, y = (threadIdx.x >> 5) * 4;
    #pragma unroll
    for (int i = 0; i < 4; i++)
        t[y+i][x] = W[(size_t)(kb + y + i)*N + nb + x];
    __syncthreads();
    #pragma unroll
    for (int i = 0; i < 4; i++){
        float v = t[x][y+i];
        __nv_bfloat16 h = __float2bfloat16(v);
        float lo = v - __bfloat162float(h);
        oh[(size_t)(nb + y + i)*K + kb + x] = h;
        ol[(size_t)(nb + y + i)*K + kb + x] = __float2bfloat16(lo);
    }
}

// ---------------------------------------------------------------------------
// Activation bf16 split (elementwise)
// ---------------------------------------------------------------------------
__global__ void __launch_bounds__(256) split_act(
    const float* __restrict__ in, __nv_bfloat16* __restrict__ oh,
    __nv_bfloat16* __restrict__ ol, int n)
{
    int i = blockIdx.x * 1024 + threadIdx.x * 4;
    if (i >= n) return;
    float4 v = *(const float4*)(in + i);
    float vv[4] = {v.x, v.y, v.z, v.w};
    __nv_bfloat16 h[4], l[4];
    #pragma unroll
    for (int j = 0; j < 4; j++){
        h[j] = __float2bfloat16(vv[j]);
        l[j] = __float2bfloat16(vv[j] - __bfloat162float(h[j]));
    }
    *(uint2*)(oh + i) = *(uint2*)h;
    *(uint2*)(ol + i) = *(uint2*)l;
}

// ---------------------------------------------------------------------------
// out = LayerNorm(res + y) * g + b   (row length 768)
// ---------------------------------------------------------------------------
__global__ void __launch_bounds__(256) add_ln(
    const float* __restrict__ res, const float* __restrict__ y,
    const float* __restrict__ gw, const float* __restrict__ bw,
    float* __restrict__ out)
{
    const int row = blockIdx.x;
    const float* r  = res + (size_t)row * Dc;
    const float* yy = y   + (size_t)row * Dc;
    float v[3];
    float s = 0.f, s2 = 0.f;
    #pragma unroll
    for (int qq = 0; qq < 3; qq++) {
        int idx = threadIdx.x + qq*256;
        float t = r[idx] + yy[idx];
        v[qq] = t; s += t; s2 += t*t;
    }
    #pragma unroll
    for (int off = 16; off; off >>= 1) {
        s  += __shfl_xor_sync(0xFFFFFFFFu, s,  off);
        s2 += __shfl_xor_sync(0xFFFFFFFFu, s2, off);
    }
    __shared__ float sh[2][8];
    const int w = threadIdx.x >> 5, lane = threadIdx.x & 31;
    if (lane == 0) { sh[0][w] = s; sh[1][w] = s2; }
    __syncthreads();
    float ts = 0.f, ts2 = 0.f;
    #pragma unroll
    for (int i = 0; i < 8; i++) { ts += sh[0][i]; ts2 += sh[1][i]; }
    const float mu  = ts  * (1.0f/768.0f);
    const float var = ts2 * (1.0f/768.0f) - mu*mu;
    const float rstd = rsqrtf(var + 1e-5f);
    #pragma unroll
    for (int qq = 0; qq < 3; qq++) {
        int idx = threadIdx.x + qq*256;
        out[(size_t)row*Dc + idx] = (v[qq] - mu) * rstd * gw[idx] + bw[idx];
    }
}

// ---------------------------------------------------------------------------
// Host launcher
// ---------------------------------------------------------------------------
extern "C" void kernel_launch(void* const* d_in, const int* in_sizes, int n_in,
                              void* d_out, int out_size)
{
    const float* x    = (const float*)d_in[0];
    const float* Wq   = (const float*)d_in[2];
    const float* Wk   = (const float*)d_in[3];
    const float* Wv   = (const float*)d_in[4];
    const float* Wo   = (const float*)d_in[5];
    const float* bo   = (const float*)d_in[6];
    const float* ln1g = (const float*)d_in[7];
    const float* ln1b = (const float*)d_in[8];
    const float* W1   = (const float*)d_in[9];
    const float* b1   = (const float*)d_in[10];
    const float* W2   = (const float*)d_in[11];
    const float* b2   = (const float*)d_in[12];
    const float* ln2g = (const float*)d_in[13];
    const float* ln2b = (const float*)d_in[14];

    float *gx, *gq, *gk, *gv, *gao, *gproj, *gh, *gf1, *gf2;
    __nv_bfloat16 *ah, *al, *wh, *wl;
    __nv_bfloat16 *qh_, *ql_, *kh_, *kl_, *vh_, *vl_;
    cudaGetSymbolAddress((void**)&gx,    g_x);
    cudaGetSymbolAddress((void**)&gq,    g_q);
    cudaGetSymbolAddress((void**)&gk,    g_k);
    cudaGetSymbolAddress((void**)&gv,    g_v);
    cudaGetSymbolAddress((void**)&gao,   g_ao);
    cudaGetSymbolAddress((void**)&gproj, g_proj);
    cudaGetSymbolAddress((void**)&gh,    g_h);
    cudaGetSymbolAddress((void**)&gf1,   g_f1);
    cudaGetSymbolAddress((void**)&gf2,   g_f2);
    cudaGetSymbolAddress((void**)&ah,    g_act_hi);
    cudaGetSymbolAddress((void**)&al,    g_act_lo);
    cudaGetSymbolAddress((void**)&wh,    g_wt_hi);
    cudaGetSymbolAddress((void**)&wl,    g_wt_lo);
    cudaGetSymbolAddress((void**)&qh_,   g_qh);
    cudaGetSymbolAddress((void**)&ql_,   g_ql);
    cudaGetSymbolAddress((void**)&kh_,   g_kh);
    cudaGetSymbolAddress((void**)&kl_,   g_kl);
    cudaGetSymbolAddress((void**)&vh_,   g_vh);
    cudaGetSymbolAddress((void**)&vl_,   g_vl);

    cudaFuncSetAttribute(gemm_tc,        cudaFuncAttributeMaxDynamicSharedMemorySize, GSM_TOTAL);
    cudaFuncSetAttribute(flash_attn_mma, cudaFuncAttributeMaxDynamicSharedMemorySize, FA2_SMEM);

    const size_t DD = (size_t)Dc*Dc, DF = (size_t)Dc*Fc;

    for (int l = 0; l < Lc; l++){
        size_t wb = (size_t)l * WT_PER_LAYER;
        transpose_split<<<dim3(Dc/32, Dc/32), 256>>>(Wq + l*DD, Dc, Dc, wh + wb,        wl + wb);
        transpose_split<<<dim3(Dc/32, Dc/32), 256>>>(Wk + l*DD, Dc, Dc, wh + wb + DD,   wl + wb + DD);
        transpose_split<<<dim3(Dc/32, Dc/32), 256>>>(Wv + l*DD, Dc, Dc, wh + wb + 2*DD, wl + wb + 2*DD);
        transpose_split<<<dim3(Dc/32, Dc/32), 256>>>(Wo + l*DD, Dc, Dc, wh + wb + 3*DD, wl + wb + 3*DD);
        transpose_split<<<dim3(Fc/32, Dc/32), 256>>>(W1 + l*DF, Dc, Fc, wh + wb + 4*DD, wl + wb + 4*DD);
        transpose_split<<<dim3(Dc/32, Fc/32), 256>>>(W2 + l*DF, Fc, Dc, wh + wb + 4*DD + DF, wl + wb + 4*DD + DF);
    }

    cudaMemcpyAsync(gx, x, (size_t)Mc*Dc*sizeof(float), cudaMemcpyDeviceToDevice);

    const dim3 gD(Dc/128, Mc/128);   // (6, 64)
    const dim3 gF(Fc/128, Mc/128);   // (24, 64)
    const int nMD = Mc*Dc, nMF = Mc*Fc;

    for (int l = 0; l < Lc; l++){
        size_t wb = (size_t)l * WT_PER_LAYER;
        const __nv_bfloat16 *qhw = wh+wb,        *qlw = wl+wb;
        const __nv_bfloat16 *khw = wh+wb+DD,     *klw = wl+wb+DD;
        const __nv_bfloat16 *vhw = wh+wb+2*DD,   *vlw = wl+wb+2*DD;
        const __nv_bfloat16 *ohw = wh+wb+3*DD,   *olw = wl+wb+3*DD;
        const __nv_bfloat16 *w1h= wh+wb+4*DD,    *w1l= wl+wb+4*DD;
        const __nv_bfloat16 *w2h= wh+wb+4*DD+DF, *w2l= wl+wb+4*DD+DF;

        split_act<<<nMD/1024, 256>>>(gx, ah, al, nMD);
        gemm_tc<<<gD, 256, GSM_TOTAL>>>(ah, al, qhw, qlw, nullptr, gq, Mc, Dc, Dc, 0);
        gemm_tc<<<gD, 256, GSM_TOTAL>>>(ah, al, khw, klw, nullptr, gk, Mc, Dc, Dc, 0);
        gemm_tc<<<gD, 256, GSM_TOTAL>>>(ah, al, vhw, vlw, nullptr, gv, Mc, Dc, Dc, 0);

        split_act<<<nMD/1024, 256>>>(gq, qh_, ql_, nMD);
        split_act<<<nMD/1024, 256>>>(gk, kh_, kl_, nMD);
        split_act<<<nMD/1024, 256>>>(gv, vh_, vl_, nMD);

        flash_attn_mma<<<dim3(Sc/64, Bc*Hc), 128, FA2_SMEM>>>(qh_, ql_, kh_, kl_, vh_, vl_, gao);

        split_act<<<nMD/1024, 256>>>(gao, ah, al, nMD);
        gemm_tc<<<gD, 256, GSM_TOTAL>>>(ah, al, ohw, olw, bo + (size_t)l*Dc, gproj, Mc, Dc, Dc, 0);
        add_ln<<<Mc, 256>>>(gx, gproj, ln1g + (size_t)l*Dc, ln1b + (size_t)l*Dc, gh);

        split_act<<<nMD/1024, 256>>>(gh, ah, al, nMD);
        gemm_tc<<<gF, 256, GSM_TOTAL>>>(ah, al, w1h, w1l, b1 + (size_t)l*Fc, gf1, Mc, Fc, Dc, 1);
        split_act<<<nMF/1024, 256>>>(gf1, ah, al, nMF);
        gemm_tc<<<gD, 256, GSM_TOTAL>>>(ah, al, w2h, w2l, b2 + (size_t)l*Dc, gf2, Mc, Dc, Fc, 0);
        add_ln<<<Mc, 256>>>(gh, gf2, ln2g + (size_t)l*Dc, ln2b + (size_t)l*Dc, gx);
    }

    cudaMemcpyAsync(d_out, gx, (size_t)Mc*Dc*sizeof(float), cudaMemcpyDeviceToDevice);
}

// round 10
// speedup vs baseline: 3.2115x; 1.0512x over previous
#include <cuda_runtime.h>
#include <cuda_bf16.h>
#include <math.h>
#include <stdint.h>

// Problem constants
#define Bc 4
#define Sc 2048
#define Dc 768
#define Hc 12
#define DHc 64
#define Fc 3072
#define Lc 4
#define Mc (Bc*Sc)   // 8192 rows
#define QKVc 2304    // 3*Dc

// ---------------------------------------------------------------------------
// Scratch (device globals; no allocation allowed)
// ---------------------------------------------------------------------------
__device__ float g_x[(size_t)Mc*Dc];      // running activation (fp32)
__device__ float g_proj[(size_t)Mc*Dc];   // attn proj / scratch fp32
__device__ float g_h[(size_t)Mc*Dc];      // post-LN1 fp32
__device__ float g_f2[(size_t)Mc*Dc];     // FFN out fp32

// split activations (width Dc): x-split / ao-split / h-split (reused)
__device__ __nv_bfloat16 g_acth[(size_t)Mc*Dc];
__device__ __nv_bfloat16 g_actl[(size_t)Mc*Dc];
// split qkv concat [Mc, 2304]
__device__ __nv_bfloat16 g_qkvh[(size_t)Mc*QKVc];
__device__ __nv_bfloat16 g_qkvl[(size_t)Mc*QKVc];
// split f1 [Mc, Fc]
__device__ __nv_bfloat16 g_f1h[(size_t)Mc*Fc];
__device__ __nv_bfloat16 g_f1l[(size_t)Mc*Fc];

// bf16 split transposed weights, all layers: [WqT;WkT;WvT;WoT;W1T;W2T]
#define WT_PER_LAYER ((size_t)4*Dc*Dc + 2*(size_t)Dc*Fc)
__device__ __nv_bfloat16 g_wt_hi[WT_PER_LAYER*Lc];
__device__ __nv_bfloat16 g_wt_lo[WT_PER_LAYER*Lc];

// ---------------------------------------------------------------------------
// Helpers
// ---------------------------------------------------------------------------
__device__ __forceinline__ uint32_t smem_u32(const void* p){
    uint32_t a;
    asm("{ .reg .u64 t; cvta.to.shared.u64 t, %1; cvt.u32.u64 %0, t; }":"=r"(a):"l"(p));
    return a;
}
__device__ __forceinline__ void cpasync16(uint32_t dst, const void* src){
    asm volatile("cp.async.cg.shared.global [%0], [%1], 16;" :: "r"(dst), "l"(src));
}
#define CP_COMMIT() asm volatile("cp.async.commit_group;" ::: "memory")

__device__ __forceinline__ void ldm_x4(uint32_t addr, uint32_t& r0, uint32_t& r1,
                                       uint32_t& r2, uint32_t& r3){
    asm volatile("ldmatrix.sync.aligned.m8n8.x4.shared.b16 {%0,%1,%2,%3}, [%4];"
        : "=r"(r0),"=r"(r1),"=r"(r2),"=r"(r3) : "r"(addr));
}
__device__ __forceinline__ void ldm_x2(uint32_t addr, uint32_t& r0, uint32_t& r1){
    asm volatile("ldmatrix.sync.aligned.m8n8.x2.shared.b16 {%0,%1}, [%2];"
        : "=r"(r0),"=r"(r1) : "r"(addr));
}
__device__ __forceinline__ void ldm_x4_t(uint32_t addr, uint32_t& r0, uint32_t& r1,
                                         uint32_t& r2, uint32_t& r3){
    asm volatile("ldmatrix.sync.aligned.m8n8.x4.trans.shared.b16 {%0,%1,%2,%3}, [%4];"
        : "=r"(r0),"=r"(r1),"=r"(r2),"=r"(r3) : "r"(addr));
}
__device__ __forceinline__ void mma_bf16(float* c, const uint32_t* a, const uint32_t* b){
    asm volatile("mma.sync.aligned.m16n8k16.row.col.f32.bf16.bf16.f32 "
        "{%0,%1,%2,%3}, {%4,%5,%6,%7}, {%8,%9}, {%0,%1,%2,%3};"
        : "+f"(c[0]),"+f"(c[1]),"+f"(c[2]),"+f"(c[3])
        : "r"(a[0]),"r"(a[1]),"r"(a[2]),"r"(a[3]), "r"(b[0]),"r"(b[1]));
}
__device__ __forceinline__ uint32_t pack_bf2(__nv_bfloat16 a, __nv_bfloat16 b){
    union { __nv_bfloat162 v; uint32_t u; } t;
    t.v.x = a; t.v.y = b; return t.u;
}
__device__ __forceinline__ uint32_t split_pack(float v0, float v1, uint32_t& lo){
    __nv_bfloat16 h0 = __float2bfloat16(v0);
    __nv_bfloat16 h1 = __float2bfloat16(v1);
    lo = pack_bf2(__float2bfloat16(v0 - __bfloat162float(h0)),
                  __float2bfloat16(v1 - __bfloat162float(h1)));
    return pack_bf2(h0, h1);
}

// ---------------------------------------------------------------------------
// mma.sync GEMM: C[M,N] = (Ah+Al)[M,K] @ (Bh+Bl)[N,K]^T  (3-term bf16 split)
// Optional fp32 output Cf and/or split bf16 output Ch/Cl (row stride ldc).
// ---------------------------------------------------------------------------
#define T_STRIDE 80
#define TILE_B   (128*T_STRIDE)
#define STAGE_B  (4*TILE_B)
#define GSM_TOTAL (2*STAGE_B)

__global__ void __launch_bounds__(256, 1) gemm_tc(
    const __nv_bfloat16* __restrict__ Ah, const __nv_bfloat16* __restrict__ Al,
    const __nv_bfloat16* __restrict__ Bh, const __nv_bfloat16* __restrict__ Bl,
    const float* __restrict__ bias,
    float* __restrict__ Cf,
    __nv_bfloat16* __restrict__ Ch, __nv_bfloat16* __restrict__ Cl,
    int M, int N, int K, int ldc, int epi)
{
    extern __shared__ char smem[];
    const uint32_t sbase = smem_u32(smem);
    const int tid = threadIdx.x;
    const int wid = tid >> 5, lane = tid & 31;
    const int warpM = wid >> 2, warpN = wid & 3;
    const int m0 = blockIdx.y * 128, n0 = blockIdx.x * 128;

    const __nv_bfloat16* srcs[4] = {Ah, Al, Bh, Bl};
    const int rowbase[4] = {m0, m0, n0, n0};

    auto load_chunk = [&](int c, int s){
        const int k0 = c * 32;
        #pragma unroll
        for (int i = 0; i < 8; i++){
            int idx = tid + i*256;
            int seg  = idx & 3;
            int row  = (idx >> 2) & 127;
            int t    = idx >> 9;
            uint32_t dst = sbase + s*STAGE_B + t*TILE_B + row*T_STRIDE + seg*16;
            const char* src = (const char*)(srcs[t] + (size_t)(rowbase[t] + row)*K + k0) + seg*16;
            cpasync16(dst, src);
        }
        CP_COMMIT();
    };

    float acc[4][4][4];
    #pragma unroll
    for (int i = 0; i < 4; i++)
        #pragma unroll
        for (int j = 0; j < 4; j++)
            #pragma unroll
            for (int r = 0; r < 4; r++) acc[i][j][r] = 0.f;

    const int NC = K / 32;
    load_chunk(0, 0);

    const uint32_t aoff = (uint32_t)(lane & 15) * T_STRIDE + (uint32_t)(lane >> 4) * 16;
    const uint32_t boff = (uint32_t)(lane & 7)  * T_STRIDE + (uint32_t)((lane >> 3) & 1) * 16;

    for (int c = 0; c < NC; c++){
        const int s = c & 1;
        if (c + 1 < NC){ load_chunk(c + 1, s ^ 1); }
        if (c + 1 < NC) asm volatile("cp.async.wait_group 1;" ::: "memory");
        else            asm volatile("cp.async.wait_group 0;" ::: "memory");
        __syncthreads();

        const uint32_t st  = sbase + s*STAGE_B;
        const uint32_t A_h = st,            A_l = st + TILE_B;
        const uint32_t B_h = st + 2*TILE_B, B_l = st + 3*TILE_B;

        #pragma unroll
        for (int ks = 0; ks < 2; ks++){
            uint32_t ah[4][4], al[4][4], bh[4][2], bl[4][2];
            #pragma unroll
            for (int i = 0; i < 4; i++){
                uint32_t ra = (uint32_t)(warpM*64 + i*16) * T_STRIDE + (uint32_t)(ks*32) + aoff;
                ldm_x4(A_h + ra, ah[i][0], ah[i][1], ah[i][2], ah[i][3]);
                ldm_x4(A_l + ra, al[i][0], al[i][1], al[i][2], al[i][3]);
            }
            #pragma unroll
            for (int j = 0; j < 4; j++){
                uint32_t rb = (uint32_t)(warpN*32 + j*8) * T_STRIDE + (uint32_t)(ks*32) + boff;
                ldm_x2(B_h + rb, bh[j][0], bh[j][1]);
                ldm_x2(B_l + rb, bl[j][0], bl[j][1]);
            }
            #pragma unroll
            for (int i = 0; i < 4; i++)
                #pragma unroll
                for (int j = 0; j < 4; j++){
                    mma_bf16(acc[i][j], ah[i], bh[j]);
                    mma_bf16(acc[i][j], ah[i], bl[j]);
                    mma_bf16(acc[i][j], al[i], bh[j]);
                }
        }
        __syncthreads();
    }

    const int gid = lane >> 2, tig = lane & 3;
    #pragma unroll
    for (int i = 0; i < 4; i++){
        #pragma unroll
        for (int j = 0; j < 4; j++){
            const int col = n0 + warpN*32 + j*8 + tig*2;
            float b0 = bias ? bias[col]     : 0.f;
            float b1 = bias ? bias[col + 1] : 0.f;
            #pragma unroll
            for (int half = 0; half < 2; half++){
                const int row = m0 + warpM*64 + i*16 + gid + half*8;
                float v0 = acc[i][j][half*2 + 0] + b0;
                float v1 = acc[i][j][half*2 + 1] + b1;
                if (epi){
                    v0 = 0.5f * v0 * (1.0f + erff(v0 * 0.70710678118654752f));
                    v1 = 0.5f * v1 * (1.0f + erff(v1 * 0.70710678118654752f));
                }
                const size_t off = (size_t)row * ldc + col;
                if (Cf) *(float2*)(Cf + off) = make_float2(v0, v1);
                if (Ch){
                    uint32_t lo, hi = split_pack(v0, v1, lo);
                    *(uint32_t*)(Ch + off) = hi;
                    *(uint32_t*)(Cl + off) = lo;
                }
            }
        }
    }
}

// ---------------------------------------------------------------------------
// Flash attention via mma.sync (causal), 3-term bf16 split, double-buffered KV.
// Input: split qkv concat [Mc, 2304] (cols: q | k | v, each head h at h*64).
// Output: split bf16 ao [Mc, 768].
// Block = 64 q rows of one (b,h); 128 threads = 4 warps.
// ---------------------------------------------------------------------------
#define AT_STRIDE 144
#define KV_STAGE  36864            // 4 arrays x 64 rows x 144B
#define FQ_H      36864            // Q lives in stage-1 region initially
#define FQ_L      46080
#define FA2_SMEM  73728

__global__ void __launch_bounds__(128) flash_attn_mma(
    const __nv_bfloat16* __restrict__ qkvh, const __nv_bfloat16* __restrict__ qkvl,
    __nv_bfloat16* __restrict__ aoh, __nv_bfloat16* __restrict__ aol)
{
    extern __shared__ char smem[];
    const uint32_t sbase = smem_u32(smem);
    const int tid = threadIdx.x;
    const int wid = tid >> 5, lane = tid & 31;
    const int gid = lane >> 2, tig = lane & 3;
    const int bh = blockIdx.y;
    const int b = bh / Hc, h = bh - b*Hc;
    const int qt = blockIdx.x;
    const int q0 = qt * 64;
    const size_t rowb = (size_t)b * Sc;      // global row base
    const int qcol = h*64, kcol = Dc + h*64, vcol = 2*Dc + h*64;

    // ---- KV loader: kt tile -> stage s (4 arrays x 64 rows x 128B)
    auto load_kv = [&](int kt, int s){
        const int k0 = kt * 64;
        const __nv_bfloat16* srcs[4] = {qkvh, qkvl, qkvh, qkvl};
        const int cols[4] = {kcol, kcol, vcol, vcol};
        #pragma unroll
        for (int i = 0; i < 16; i++){
            int idx = tid + i*128;            // 0..2047
            int arr = idx >> 9;               // 0..3
            int rem = idx & 511;
            int row = rem >> 3, ch = rem & 7;
            const char* src = (const char*)(srcs[arr] + (rowb + k0 + row)*QKVc + cols[arr]) + ch*16;
            cpasync16(sbase + s*KV_STAGE + arr*9216 + row*AT_STRIDE + ch*16, src);
        }
        CP_COMMIT();
    };

    // ---- prologue: load Q (into stage-1 region) + KV tile 0 (stage 0)
    {
        #pragma unroll
        for (int i = 0; i < 8; i++){
            int idx = tid + i*128;            // 0..1023
            int arr = idx >> 9;               // 0..1
            int rem = idx & 511;
            int row = rem >> 3, ch = rem & 7;
            const __nv_bfloat16* sp = arr ? qkvl : qkvh;
            const char* src = (const char*)(sp + (rowb + q0 + row)*QKVc + qcol) + ch*16;
            cpasync16(sbase + (arr ? FQ_L : FQ_H) + row*AT_STRIDE + ch*16, src);
        }
        load_kv(0, 0);
    }
    asm volatile("cp.async.wait_group 0;" ::: "memory");
    __syncthreads();

    // ---- Q fragments into registers
    uint32_t qhf[4][4], qlf[4][4];
    {
        const uint32_t ao_ = (uint32_t)(lane & 15)*AT_STRIDE + (uint32_t)(lane >> 4)*16;
        #pragma unroll
        for (int ks = 0; ks < 4; ks++){
            uint32_t ra = (uint32_t)(wid*16)*AT_STRIDE + (uint32_t)(ks*32) + ao_;
            ldm_x4(sbase + FQ_H + ra, qhf[ks][0], qhf[ks][1], qhf[ks][2], qhf[ks][3]);
            ldm_x4(sbase + FQ_L + ra, qlf[ks][0], qlf[ks][1], qlf[ks][2], qlf[ks][3]);
        }
    }
    __syncthreads();   // Q reads done before stage-1 gets overwritten

    float accO[8][4];
    #pragma unroll
    for (int j = 0; j < 8; j++)
        #pragma unroll
        for (int c = 0; c < 4; c++) accO[j][c] = 0.f;
    float m_run[2] = {-1e30f, -1e30f};
    float l_run[2] = {0.f, 0.f};

    const uint32_t boff4 = (uint32_t)((lane & 7) + ((lane >> 4) << 3))*AT_STRIDE
                         + (uint32_t)((lane >> 3) & 1)*16;
    const uint32_t voff4 = (uint32_t)(lane & 15)*AT_STRIDE + (uint32_t)(lane >> 4)*16;

    const int row0 = q0 + wid*16 + gid;
    const int row1 = row0 + 8;

    for (int kt = 0; kt <= qt; kt++){
        const int s = kt & 1;
        if (kt > 0){
            asm volatile("cp.async.wait_group 0;" ::: "memory");
            __syncthreads();
        }
        if (kt < qt) load_kv(kt + 1, s ^ 1);

        const uint32_t K_h = sbase + s*KV_STAGE;
        const uint32_t K_l = K_h + 9216;
        const uint32_t V_h = K_h + 18432;
        const uint32_t V_l = K_h + 27648;

        // ---- S = Q K^T (3 terms)
        float accS[8][4];
        #pragma unroll
        for (int j = 0; j < 8; j++)
            #pragma unroll
            for (int c = 0; c < 4; c++) accS[j][c] = 0.f;

        #pragma unroll
        for (int ks = 0; ks < 4; ks++){
            #pragma unroll
            for (int jj = 0; jj < 4; jj++){
                uint32_t rb = (uint32_t)(jj*16)*AT_STRIDE + (uint32_t)(ks*32) + boff4;
                uint32_t bh4[4], bl4[4];
                ldm_x4(K_h + rb, bh4[0], bh4[1], bh4[2], bh4[3]);
                ldm_x4(K_l + rb, bl4[0], bl4[1], bl4[2], bl4[3]);
                mma_bf16(accS[2*jj],   qhf[ks], bh4 + 0);
                mma_bf16(accS[2*jj],   qhf[ks], bl4 + 0);
                mma_bf16(accS[2*jj],   qlf[ks], bh4 + 0);
                mma_bf16(accS[2*jj+1], qhf[ks], bh4 + 2);
                mma_bf16(accS[2*jj+1], qhf[ks], bl4 + 2);
                mma_bf16(accS[2*jj+1], qlf[ks], bh4 + 2);
            }
        }

        // ---- scale + causal mask on diagonal tile
        const bool diag = (kt == qt);
        const int k0 = kt * 64;
        #pragma unroll
        for (int j = 0; j < 8; j++){
            #pragma unroll
            for (int c = 0; c < 4; c++){
                float sv = accS[j][c] * 0.125f;
                if (diag){
                    int col = k0 + j*8 + tig*2 + (c & 1);
                    int row = (c < 2) ? row0 : row1;
                    if (col > row) sv = -1e30f;
                }
                accS[j][c] = sv;
            }
        }

        // ---- online softmax
        #pragma unroll
        for (int half = 0; half < 2; half++){
            float mloc = -1e30f;
            #pragma unroll
            for (int j = 0; j < 8; j++){
                mloc = fmaxf(mloc, accS[j][half*2]);
                mloc = fmaxf(mloc, accS[j][half*2+1]);
            }
            mloc = fmaxf(mloc, __shfl_xor_sync(0xFFFFFFFFu, mloc, 1));
            mloc = fmaxf(mloc, __shfl_xor_sync(0xFFFFFFFFu, mloc, 2));
            const float mnew = fmaxf(m_run[half], mloc);
            const float alpha = __expf(m_run[half] - mnew);
            m_run[half] = mnew;
            float psum = 0.f;
            #pragma unroll
            for (int j = 0; j < 8; j++){
                float p0 = __expf(accS[j][half*2]   - mnew);
                float p1 = __expf(accS[j][half*2+1] - mnew);
                accS[j][half*2]   = p0;
                accS[j][half*2+1] = p1;
                psum += p0 + p1;
            }
            psum += __shfl_xor_sync(0xFFFFFFFFu, psum, 1);
            psum += __shfl_xor_sync(0xFFFFFFFFu, psum, 2);
            l_run[half] = l_run[half]*alpha + psum;
            #pragma unroll
            for (int j = 0; j < 8; j++){
                accO[j][half*2]   *= alpha;
                accO[j][half*2+1] *= alpha;
            }
        }

        // ---- O += P V (3 terms)
        #pragma unroll
        for (int ks = 0; ks < 4; ks++){
            uint32_t aPh[4], aPl[4];
            #pragma unroll
            for (int t = 0; t < 4; t++){
                const int j = 2*ks + (t >> 1);
                const int c0 = (t & 1)*2;
                aPh[t] = split_pack(accS[j][c0], accS[j][c0+1], aPl[t]);
            }
            #pragma unroll
            for (int jj = 0; jj < 4; jj++){
                uint32_t rv = (uint32_t)(ks*16)*AT_STRIDE + (uint32_t)(jj*32) + voff4;
                uint32_t vh4[4], vl4[4];
                ldm_x4_t(V_h + rv, vh4[0], vh4[1], vh4[2], vh4[3]);
                ldm_x4_t(V_l + rv, vl4[0], vl4[1], vl4[2], vl4[3]);
                mma_bf16(accO[2*jj],   aPh, vh4 + 0);
                mma_bf16(accO[2*jj],   aPh, vl4 + 0);
                mma_bf16(accO[2*jj],   aPl, vh4 + 0);
                mma_bf16(accO[2*jj+1], aPh, vh4 + 2);
                mma_bf16(accO[2*jj+1], aPh, vl4 + 2);
                mma_bf16(accO[2*jj+1], aPl, vh4 + 2);
            }
        }
    }

    // ---- write O as split bf16 into ao [Mc, 768]
    const float rl0 = 1.0f / l_run[0];
    const float rl1 = 1.0f / l_run[1];
    #pragma unroll
    for (int j = 0; j < 8; j++){
        const int col = h*64 + j*8 + tig*2;
        const size_t o0 = (rowb + row0)*Dc + col;
        const size_t o1 = (rowb + row1)*Dc + col;
        uint32_t lo, hi;
        hi = split_pack(accO[j][0]*rl0, accO[j][1]*rl0, lo);
        *(uint32_t*)(aoh + o0) = hi; *(uint32_t*)(aol + o0) = lo;
        hi = split_pack(accO[j][2]*rl1, accO[j][3]*rl1, lo);
        *(uint32_t*)(aoh + o1) = hi; *(uint32_t*)(aol + o1) = lo;
    }
}

// ---------------------------------------------------------------------------
// Weight transpose + bf16 split:  W[K,N] fp32 -> out_hi/lo[N,K] bf16
// ---------------------------------------------------------------------------
__global__ void __launch_bounds__(256) transpose_split(
    const float* __restrict__ W, int K, int N,
    __nv_bfloat16* __restrict__ oh, __nv_bfloat16* __restrict__ ol)
{
    __shared__ float t[32][33];
    const int kb = blockIdx.y*32, nb = blockIdx.x*32;
    const int x = threadIdx.x & 31, y = (threadIdx.x >> 5) * 4;
    #pragma unroll
    for (int i = 0; i < 4; i++)
        t[y+i][x] = W[(size_t)(kb + y + i)*N + nb + x];
    __syncthreads();
    #pragma unroll
    for (int i = 0; i < 4; i++){
        float v = t[x][y+i];
        __nv_bfloat16 h = __float2bfloat16(v);
        float lo = v - __bfloat162float(h);
        oh[(size_t)(nb + y + i)*K + kb + x] = h;
        ol[(size_t)(nb + y + i)*K + kb + x] = __float2bfloat16(lo);
    }
}

// ---------------------------------------------------------------------------
// Activation bf16 split (elementwise) — only used for the initial x
// ---------------------------------------------------------------------------
__global__ void __launch_bounds__(256) split_act(
    const float* __restrict__ in, __nv_bfloat16* __restrict__ oh,
    __nv_bfloat16* __restrict__ ol, int n)
{
    int i = blockIdx.x * 1024 + threadIdx.x * 4;
    if (i >= n) return;
    float4 v = *(const float4*)(in + i);
    float vv[4] = {v.x, v.y, v.z, v.w};
    __nv_bfloat16 h[4], l[4];
    #pragma unroll
    for (int j = 0; j < 4; j++){
        h[j] = __float2bfloat16(vv[j]);
        l[j] = __float2bfloat16(vv[j] - __bfloat162float(h[j]));
    }
    *(uint2*)(oh + i) = *(uint2*)h;
    *(uint2*)(ol + i) = *(uint2*)l;
}

// ---------------------------------------------------------------------------
// out = LayerNorm(res + y) * g + b  -> fp32 out + split bf16 (oh/ol)
// ---------------------------------------------------------------------------
__global__ void __launch_bounds__(256) add_ln(
    const float* __restrict__ res, const float* __restrict__ y,
    const float* __restrict__ gw, const float* __restrict__ bw,
    float* __restrict__ out,
    __nv_bfloat16* __restrict__ oh, __nv_bfloat16* __restrict__ ol)
{
    const int row = blockIdx.x;
    const float* r  = res + (size_t)row * Dc;
    const float* yy = y   + (size_t)row * Dc;
    float v[3];
    float s = 0.f, s2 = 0.f;
    #pragma unroll
    for (int qq = 0; qq < 3; qq++) {
        int idx = threadIdx.x + qq*256;
        float t = r[idx] + yy[idx];
        v[qq] = t; s += t; s2 += t*t;
    }
    #pragma unroll
    for (int off = 16; off; off >>= 1) {
        s  += __shfl_xor_sync(0xFFFFFFFFu, s,  off);
        s2 += __shfl_xor_sync(0xFFFFFFFFu, s2, off);
    }
    __shared__ float sh[2][8];
    const int w = threadIdx.x >> 5, lane = threadIdx.x & 31;
    if (lane == 0) { sh[0][w] = s; sh[1][w] = s2; }
    __syncthreads();
    float ts = 0.f, ts2 = 0.f;
    #pragma unroll
    for (int i = 0; i < 8; i++) { ts += sh[0][i]; ts2 += sh[1][i]; }
    const float mu  = ts  * (1.0f/768.0f);
    const float var = ts2 * (1.0f/768.0f) - mu*mu;
    const float rstd = rsqrtf(var + 1e-5f);
    #pragma unroll
    for (int qq = 0; qq < 3; qq++) {
        int idx = threadIdx.x + qq*256;
        float o = (v[qq] - mu) * rstd * gw[idx] + bw[idx];
        const size_t off = (size_t)row*Dc + idx;
        out[off] = o;
        __nv_bfloat16 hh = __float2bfloat16(o);
        oh[off] = hh;
        ol[off] = __float2bfloat16(o - __bfloat162float(hh));
    }
}

// ---------------------------------------------------------------------------
// Host launcher
// ---------------------------------------------------------------------------
extern "C" void kernel_launch(void* const* d_in, const int* in_sizes, int n_in,
                              void* d_out, int out_size)
{
    const float* x    = (const float*)d_in[0];
    const float* Wq   = (const float*)d_in[2];
    const float* Wk   = (const float*)d_in[3];
    const float* Wv   = (const float*)d_in[4];
    const float* Wo   = (const float*)d_in[5];
    const float* bo   = (const float*)d_in[6];
    const float* ln1g = (const float*)d_in[7];
    const float* ln1b = (const float*)d_in[8];
    const float* W1   = (const float*)d_in[9];
    const float* b1   = (const float*)d_in[10];
    const float* W2   = (const float*)d_in[11];
    const float* b2   = (const float*)d_in[12];
    const float* ln2g = (const float*)d_in[13];
    const float* ln2b = (const float*)d_in[14];

    float *gx, *gproj, *gh, *gf2;
    __nv_bfloat16 *acth, *actl, *qkvh, *qkvl, *f1h, *f1l, *wh, *wl;
    cudaGetSymbolAddress((void**)&gx,    g_x);
    cudaGetSymbolAddress((void**)&gproj, g_proj);
    cudaGetSymbolAddress((void**)&gh,    g_h);
    cudaGetSymbolAddress((void**)&gf2,   g_f2);
    cudaGetSymbolAddress((void**)&acth,  g_acth);
    cudaGetSymbolAddress((void**)&actl,  g_actl);
    cudaGetSymbolAddress((void**)&qkvh,  g_qkvh);
    cudaGetSymbolAddress((void**)&qkvl,  g_qkvl);
    cudaGetSymbolAddress((void**)&f1h,   g_f1h);
    cudaGetSymbolAddress((void**)&f1l,   g_f1l);
    cudaGetSymbolAddress((void**)&wh,    g_wt_hi);
    cudaGetSymbolAddress((void**)&wl,    g_wt_lo);

    cudaFuncSetAttribute(gemm_tc,        cudaFuncAttributeMaxDynamicSharedMemorySize, GSM_TOTAL);
    cudaFuncSetAttribute(flash_attn_mma, cudaFuncAttributeMaxDynamicSharedMemorySize, FA2_SMEM);

    const size_t DD = (size_t)Dc*Dc, DF = (size_t)Dc*Fc;

    // weight prep: transpose + split all layers ([q;k;v] contiguous per layer)
    for (int l = 0; l < Lc; l++){
        size_t wb = (size_t)l * WT_PER_LAYER;
        transpose_split<<<dim3(Dc/32, Dc/32), 256>>>(Wq + l*DD, Dc, Dc, wh + wb,        wl + wb);
        transpose_split<<<dim3(Dc/32, Dc/32), 256>>>(Wk + l*DD, Dc, Dc, wh + wb + DD,   wl + wb + DD);
        transpose_split<<<dim3(Dc/32, Dc/32), 256>>>(Wv + l*DD, Dc, Dc, wh + wb + 2*DD, wl + wb + 2*DD);
        transpose_split<<<dim3(Dc/32, Dc/32), 256>>>(Wo + l*DD, Dc, Dc, wh + wb + 3*DD, wl + wb + 3*DD);
        transpose_split<<<dim3(Fc/32, Dc/32), 256>>>(W1 + l*DF, Dc, Fc, wh + wb + 4*DD, wl + wb + 4*DD);
        transpose_split<<<dim3(Dc/32, Fc/32), 256>>>(W2 + l*DF, Fc, Dc, wh + wb + 4*DD + DF, wl + wb + 4*DD + DF);
    }

    cudaMemcpyAsync(gx, x, (size_t)Mc*Dc*sizeof(float), cudaMemcpyDeviceToDevice);
    split_act<<<(Mc*Dc)/1024, 256>>>(gx, acth, actl, Mc*Dc);

    const dim3 gQKV(QKVc/128, Mc/128);  // (18, 64)
    const dim3 gD(Dc/128, Mc/128);      // (6, 64)
    const dim3 gF(Fc/128, Mc/128);      // (24, 64)

    for (int l = 0; l < Lc; l++){
        size_t wb = (size_t)l * WT_PER_LAYER;
        const __nv_bfloat16 *qkvw_h = wh+wb,         *qkvw_l = wl+wb;        // [2304,768]
        const __nv_bfloat16 *ohw = wh+wb+3*DD,       *olw = wl+wb+3*DD;
        const __nv_bfloat16 *w1h = wh+wb+4*DD,       *w1l = wl+wb+4*DD;
        const __nv_bfloat16 *w2h = wh+wb+4*DD+DF,    *w2l = wl+wb+4*DD+DF;

        // fused QKV -> split qkv concat
        gemm_tc<<<gQKV, 256, GSM_TOTAL>>>(acth, actl, qkvw_h, qkvw_l, nullptr,
                                          nullptr, qkvh, qkvl, Mc, QKVc, Dc, QKVc, 0);
        // attention -> split ao (into act buffers)
        flash_attn_mma<<<dim3(Sc/64, Bc*Hc), 128, FA2_SMEM>>>(qkvh, qkvl, acth, actl);
        // Wo proj -> fp32
        gemm_tc<<<gD, 256, GSM_TOTAL>>>(acth, actl, ohw, olw, bo + (size_t)l*Dc,
                                        gproj, nullptr, nullptr, Mc, Dc, Dc, Dc, 0);
        // LN1 -> fp32 h + split h
        add_ln<<<Mc, 256>>>(gx, gproj, ln1g + (size_t)l*Dc, ln1b + (size_t)l*Dc,
                            gh, acth, actl);
        // FFN1 + GELU -> split f1
        gemm_tc<<<gF, 256, GSM_TOTAL>>>(acth, actl, w1h, w1l, b1 + (size_t)l*Fc,
                                        nullptr, f1h, f1l, Mc, Fc, Dc, Fc, 1);
        // FFN2 -> fp32
        gemm_tc<<<gD, 256, GSM_TOTAL>>>(f1h, f1l, w2h, w2l, b2 + (size_t)l*Dc,
                                        gf2, nullptr, nullptr, Mc, Dc, Fc, Dc, 0);
        // LN2 -> fp32 x + split x (next layer input)
        add_ln<<<Mc, 256>>>(gh, gf2, ln2g + (size_t)l*Dc, ln2b + (size_t)l*Dc,
                            gx, acth, actl);
    }

    cudaMemcpyAsync(d_out, gx, (size_t)Mc*Dc*sizeof(float), cudaMemcpyDeviceToDevice);
}

// round 12
// speedup vs baseline: 3.6437x; 1.1346x over previous
#include <cuda_runtime.h>
#include <cuda_bf16.h>
#include <math.h>
#include <stdint.h>

// Problem constants
#define Bc 4
#define Sc 2048
#define Dc 768
#define Hc 12
#define DHc 64
#define Fc 3072
#define Lc 4
#define Mc (Bc*Sc)   // 8192 rows
#define QKVc 2304    // 3*Dc

// ---------------------------------------------------------------------------
// Scratch (device globals; no allocation allowed)
// ---------------------------------------------------------------------------
__device__ float g_x[(size_t)Mc*Dc];
__device__ float g_proj[(size_t)Mc*Dc];
__device__ float g_h[(size_t)Mc*Dc];
__device__ float g_f2[(size_t)Mc*Dc];

__device__ __nv_bfloat16 g_acth[(size_t)Mc*Dc];
__device__ __nv_bfloat16 g_actl[(size_t)Mc*Dc];
__device__ __nv_bfloat16 g_qkvh[(size_t)Mc*QKVc];
__device__ __nv_bfloat16 g_qkvl[(size_t)Mc*QKVc];
__device__ __nv_bfloat16 g_f1h[(size_t)Mc*Fc];
__device__ __nv_bfloat16 g_f1l[(size_t)Mc*Fc];

#define WT_PER_LAYER ((size_t)4*Dc*Dc + 2*(size_t)Dc*Fc)
__device__ __nv_bfloat16 g_wt_hi[WT_PER_LAYER*Lc];
__device__ __nv_bfloat16 g_wt_lo[WT_PER_LAYER*Lc];

// ---------------------------------------------------------------------------
// Helpers
// ---------------------------------------------------------------------------
__device__ __forceinline__ uint32_t smem_u32(const void* p){
    uint32_t a;
    asm("{ .reg .u64 t; cvta.to.shared.u64 t, %1; cvt.u32.u64 %0, t; }":"=r"(a):"l"(p));
    return a;
}
__device__ __forceinline__ void cpasync16(uint32_t dst, const void* src){
    asm volatile("cp.async.cg.shared.global [%0], [%1], 16;" :: "r"(dst), "l"(src));
}
#define CP_COMMIT() asm volatile("cp.async.commit_group;" ::: "memory")

__device__ __forceinline__ void ldm_x4(uint32_t addr, uint32_t& r0, uint32_t& r1,
                                       uint32_t& r2, uint32_t& r3){
    asm volatile("ldmatrix.sync.aligned.m8n8.x4.shared.b16 {%0,%1,%2,%3}, [%4];"
        : "=r"(r0),"=r"(r1),"=r"(r2),"=r"(r3) : "r"(addr));
}
__device__ __forceinline__ void ldm_x2(uint32_t addr, uint32_t& r0, uint32_t& r1){
    asm volatile("ldmatrix.sync.aligned.m8n8.x2.shared.b16 {%0,%1}, [%2];"
        : "=r"(r0),"=r"(r1) : "r"(addr));
}
__device__ __forceinline__ void ldm_x4_t(uint32_t addr, uint32_t& r0, uint32_t& r1,
                                         uint32_t& r2, uint32_t& r3){
    asm volatile("ldmatrix.sync.aligned.m8n8.x4.trans.shared.b16 {%0,%1,%2,%3}, [%4];"
        : "=r"(r0),"=r"(r1),"=r"(r2),"=r"(r3) : "r"(addr));
}
__device__ __forceinline__ void mma_bf16(float* c, const uint32_t* a, const uint32_t* b){
    asm volatile("mma.sync.aligned.m16n8k16.row.col.f32.bf16.bf16.f32 "
        "{%0,%1,%2,%3}, {%4,%5,%6,%7}, {%8,%9}, {%0,%1,%2,%3};"
        : "+f"(c[0]),"+f"(c[1]),"+f"(c[2]),"+f"(c[3])
        : "r"(a[0]),"r"(a[1]),"r"(a[2]),"r"(a[3]), "r"(b[0]),"r"(b[1]));
}
__device__ __forceinline__ uint32_t pack_bf2(__nv_bfloat16 a, __nv_bfloat16 b){
    union { __nv_bfloat162 v; uint32_t u; } t;
    t.v.x = a; t.v.y = b; return t.u;
}
__device__ __forceinline__ uint32_t split_pack(float v0, float v1, uint32_t& lo){
    __nv_bfloat16 h0 = __float2bfloat16(v0);
    __nv_bfloat16 h1 = __float2bfloat16(v1);
    lo = pack_bf2(__float2bfloat16(v0 - __bfloat162float(h0)),
                  __float2bfloat16(v1 - __bfloat162float(h1)));
    return pack_bf2(h0, h1);
}

// ---------------------------------------------------------------------------
// mma.sync GEMM (3-term bf16 split), tuned for 2 CTAs/SM.
// ---------------------------------------------------------------------------
#define T_STRIDE 80
#define TILE_B   (128*T_STRIDE)
#define STAGE_B  (4*TILE_B)
#define GSM_TOTAL (2*STAGE_B)    // 80 KB -> 2 CTAs fit in 228 KB

__global__ void __launch_bounds__(256, 2) gemm_tc(
    const __nv_bfloat16* __restrict__ Ah, const __nv_bfloat16* __restrict__ Al,
    const __nv_bfloat16* __restrict__ Bh, const __nv_bfloat16* __restrict__ Bl,
    const float* __restrict__ bias,
    float* __restrict__ Cf,
    __nv_bfloat16* __restrict__ Ch, __nv_bfloat16* __restrict__ Cl,
    int M, int N, int K, int ldc, int epi)
{
    extern __shared__ char smem[];
    const uint32_t sbase = smem_u32(smem);
    const int tid = threadIdx.x;
    const int wid = tid >> 5, lane = tid & 31;
    const int warpM = wid >> 2, warpN = wid & 3;
    const int m0 = blockIdx.y * 128, n0 = blockIdx.x * 128;

    const __nv_bfloat16* srcs[4] = {Ah, Al, Bh, Bl};
    const int rowbase[4] = {m0, m0, n0, n0};

    auto load_chunk = [&](int c, int s){
        const int k0 = c * 32;
        #pragma unroll
        for (int i = 0; i < 8; i++){
            int idx = tid + i*256;
            int seg  = idx & 3;
            int row  = (idx >> 2) & 127;
            int t    = idx >> 9;
            uint32_t dst = sbase + s*STAGE_B + t*TILE_B + row*T_STRIDE + seg*16;
            const char* src = (const char*)(srcs[t] + (size_t)(rowbase[t] + row)*K + k0) + seg*16;
            cpasync16(dst, src);
        }
        CP_COMMIT();
    };

    float acc[4][4][4];
    #pragma unroll
    for (int i = 0; i < 4; i++)
        #pragma unroll
        for (int j = 0; j < 4; j++)
            #pragma unroll
            for (int r = 0; r < 4; r++) acc[i][j][r] = 0.f;

    const int NC = K / 32;
    load_chunk(0, 0);

    const uint32_t aoff = (uint32_t)(lane & 15) * T_STRIDE + (uint32_t)(lane >> 4) * 16;
    const uint32_t boff = (uint32_t)(lane & 7)  * T_STRIDE + (uint32_t)((lane >> 3) & 1) * 16;

    for (int c = 0; c < NC; c++){
        const int s = c & 1;
        if (c + 1 < NC){ load_chunk(c + 1, s ^ 1); }
        if (c + 1 < NC) asm volatile("cp.async.wait_group 1;" ::: "memory");
        else            asm volatile("cp.async.wait_group 0;" ::: "memory");
        __syncthreads();

        const uint32_t st  = sbase + s*STAGE_B;
        const uint32_t A_h = st,            A_l = st + TILE_B;
        const uint32_t B_h = st + 2*TILE_B, B_l = st + 3*TILE_B;

        #pragma unroll
        for (int ks = 0; ks < 2; ks++){
            // hoist B fragments (16 regs live), stream A per-i (8 regs live)
            uint32_t bh[4][2], bl[4][2];
            #pragma unroll
            for (int j = 0; j < 4; j++){
                uint32_t rb = (uint32_t)(warpN*32 + j*8) * T_STRIDE + (uint32_t)(ks*32) + boff;
                ldm_x2(B_h + rb, bh[j][0], bh[j][1]);
                ldm_x2(B_l + rb, bl[j][0], bl[j][1]);
            }
            #pragma unroll
            for (int i = 0; i < 4; i++){
                uint32_t ah4[4], al4[4];
                uint32_t ra = (uint32_t)(warpM*64 + i*16) * T_STRIDE + (uint32_t)(ks*32) + aoff;
                ldm_x4(A_h + ra, ah4[0], ah4[1], ah4[2], ah4[3]);
                ldm_x4(A_l + ra, al4[0], al4[1], al4[2], al4[3]);
                #pragma unroll
                for (int j = 0; j < 4; j++){
                    mma_bf16(acc[i][j], ah4, bh[j]);
                    mma_bf16(acc[i][j], ah4, bl[j]);
                    mma_bf16(acc[i][j], al4, bh[j]);
                }
            }
        }
        __syncthreads();
    }

    const int gid = lane >> 2, tig = lane & 3;
    #pragma unroll
    for (int i = 0; i < 4; i++){
        #pragma unroll
        for (int j = 0; j < 4; j++){
            const int col = n0 + warpN*32 + j*8 + tig*2;
            float b0 = bias ? bias[col]     : 0.f;
            float b1 = bias ? bias[col + 1] : 0.f;
            #pragma unroll
            for (int half = 0; half < 2; half++){
                const int row = m0 + warpM*64 + i*16 + gid + half*8;
                float v0 = acc[i][j][half*2 + 0] + b0;
                float v1 = acc[i][j][half*2 + 1] + b1;
                if (epi){
                    v0 = 0.5f * v0 * (1.0f + erff(v0 * 0.70710678118654752f));
                    v1 = 0.5f * v1 * (1.0f + erff(v1 * 0.70710678118654752f));
                }
                const size_t off = (size_t)row * ldc + col;
                if (Cf) *(float2*)(Cf + off) = make_float2(v0, v1);
                if (Ch){
                    uint32_t lo, hi = split_pack(v0, v1, lo);
                    *(uint32_t*)(Ch + off) = hi;
                    *(uint32_t*)(Cl + off) = lo;
                }
            }
        }
    }
}

// ---------------------------------------------------------------------------
// Flash attention via mma.sync (causal), split everywhere, double-buffered KV.
// CTA order reversed so longest q-tiles run first.
// ---------------------------------------------------------------------------
#define AT_STRIDE 144
#define KV_STAGE  36864
#define FQ_H      36864
#define FQ_L      46080
#define FA2_SMEM  73728

__global__ void __launch_bounds__(128) flash_attn_mma(
    const __nv_bfloat16* __restrict__ qkvh, const __nv_bfloat16* __restrict__ qkvl,
    __nv_bfloat16* __restrict__ aoh, __nv_bfloat16* __restrict__ aol)
{
    extern __shared__ char smem[];
    const uint32_t sbase = smem_u32(smem);
    const int tid = threadIdx.x;
    const int wid = tid >> 5, lane = tid & 31;
    const int gid = lane >> 2, tig = lane & 3;
    const int bh = blockIdx.y;
    const int b = bh / Hc, h = bh - b*Hc;
    const int qt = (int)gridDim.x - 1 - (int)blockIdx.x;   // longest first
    const int q0 = qt * 64;
    const size_t rowb = (size_t)b * Sc;
    const int qcol = h*64, kcol = Dc + h*64, vcol = 2*Dc + h*64;

    auto load_kv = [&](int kt, int s){
        const int k0 = kt * 64;
        const __nv_bfloat16* srcs[4] = {qkvh, qkvl, qkvh, qkvl};
        const int cols[4] = {kcol, kcol, vcol, vcol};
        #pragma unroll
        for (int i = 0; i < 16; i++){
            int idx = tid + i*128;
            int arr = idx >> 9;
            int rem = idx & 511;
            int row = rem >> 3, ch = rem & 7;
            const char* src = (const char*)(srcs[arr] + (rowb + k0 + row)*QKVc + cols[arr]) + ch*16;
            cpasync16(sbase + s*KV_STAGE + arr*9216 + row*AT_STRIDE + ch*16, src);
        }
        CP_COMMIT();
    };

    {
        #pragma unroll
        for (int i = 0; i < 8; i++){
            int idx = tid + i*128;
            int arr = idx >> 9;
            int rem = idx & 511;
            int row = rem >> 3, ch = rem & 7;
            const __nv_bfloat16* sp = arr ? qkvl : qkvh;
            const char* src = (const char*)(sp + (rowb + q0 + row)*QKVc + qcol) + ch*16;
            cpasync16(sbase + (arr ? FQ_L : FQ_H) + row*AT_STRIDE + ch*16, src);
        }
        load_kv(0, 0);
    }
    asm volatile("cp.async.wait_group 0;" ::: "memory");
    __syncthreads();

    uint32_t qhf[4][4], qlf[4][4];
    {
        const uint32_t ao_ = (uint32_t)(lane & 15)*AT_STRIDE + (uint32_t)(lane >> 4)*16;
        #pragma unroll
        for (int ks = 0; ks < 4; ks++){
            uint32_t ra = (uint32_t)(wid*16)*AT_STRIDE + (uint32_t)(ks*32) + ao_;
            ldm_x4(sbase + FQ_H + ra, qhf[ks][0], qhf[ks][1], qhf[ks][2], qhf[ks][3]);
            ldm_x4(sbase + FQ_L + ra, qlf[ks][0], qlf[ks][1], qlf[ks][2], qlf[ks][3]);
        }
    }
    __syncthreads();

    float accO[8][4];
    #pragma unroll
    for (int j = 0; j < 8; j++)
        #pragma unroll
        for (int c = 0; c < 4; c++) accO[j][c] = 0.f;
    float m_run[2] = {-1e30f, -1e30f};
    float l_run[2] = {0.f, 0.f};

    const uint32_t boff4 = (uint32_t)((lane & 7) + ((lane >> 4) << 3))*AT_STRIDE
                         + (uint32_t)((lane >> 3) & 1)*16;
    const uint32_t voff4 = (uint32_t)(lane & 15)*AT_STRIDE + (uint32_t)(lane >> 4)*16;

    const int row0 = q0 + wid*16 + gid;
    const int row1 = row0 + 8;

    for (int kt = 0; kt <= qt; kt++){
        const int s = kt & 1;
        if (kt > 0){
            asm volatile("cp.async.wait_group 0;" ::: "memory");
            __syncthreads();
        }
        if (kt < qt) load_kv(kt + 1, s ^ 1);

        const uint32_t K_h = sbase + s*KV_STAGE;
        const uint32_t K_l = K_h + 9216;
        const uint32_t V_h = K_h + 18432;
        const uint32_t V_l = K_h + 27648;

        float accS[8][4];
        #pragma unroll
        for (int j = 0; j < 8; j++)
            #pragma unroll
            for (int c = 0; c < 4; c++) accS[j][c] = 0.f;

        #pragma unroll
        for (int ks = 0; ks < 4; ks++){
            #pragma unroll
            for (int jj = 0; jj < 4; jj++){
                uint32_t rb = (uint32_t)(jj*16)*AT_STRIDE + (uint32_t)(ks*32) + boff4;
                uint32_t bh4[4], bl4[4];
                ldm_x4(K_h + rb, bh4[0], bh4[1], bh4[2], bh4[3]);
                ldm_x4(K_l + rb, bl4[0], bl4[1], bl4[2], bl4[3]);
                mma_bf16(accS[2*jj],   qhf[ks], bh4 + 0);
                mma_bf16(accS[2*jj],   qhf[ks], bl4 + 0);
                mma_bf16(accS[2*jj],   qlf[ks], bh4 + 0);
                mma_bf16(accS[2*jj+1], qhf[ks], bh4 + 2);
                mma_bf16(accS[2*jj+1], qhf[ks], bl4 + 2);
                mma_bf16(accS[2*jj+1], qlf[ks], bh4 + 2);
            }
        }

        const bool diag = (kt == qt);
        const int k0 = kt * 64;
        #pragma unroll
        for (int j = 0; j < 8; j++){
            #pragma unroll
            for (int c = 0; c < 4; c++){
                float sv = accS[j][c] * 0.125f;
                if (diag){
                    int col = k0 + j*8 + tig*2 + (c & 1);
                    int row = (c < 2) ? row0 : row1;
                    if (col > row) sv = -1e30f;
                }
                accS[j][c] = sv;
            }
        }

        #pragma unroll
        for (int half = 0; half < 2; half++){
            float mloc = -1e30f;
            #pragma unroll
            for (int j = 0; j < 8; j++){
                mloc = fmaxf(mloc, accS[j][half*2]);
                mloc = fmaxf(mloc, accS[j][half*2+1]);
            }
            mloc = fmaxf(mloc, __shfl_xor_sync(0xFFFFFFFFu, mloc, 1));
            mloc = fmaxf(mloc, __shfl_xor_sync(0xFFFFFFFFu, mloc, 2));
            const float mnew = fmaxf(m_run[half], mloc);
            const float alpha = __expf(m_run[half] - mnew);
            m_run[half] = mnew;
            float psum = 0.f;
            #pragma unroll
            for (int j = 0; j < 8; j++){
                float p0 = __expf(accS[j][half*2]   - mnew);
                float p1 = __expf(accS[j][half*2+1] - mnew);
                accS[j][half*2]   = p0;
                accS[j][half*2+1] = p1;
                psum += p0 + p1;
            }
            psum += __shfl_xor_sync(0xFFFFFFFFu, psum, 1);
            psum += __shfl_xor_sync(0xFFFFFFFFu, psum, 2);
            l_run[half] = l_run[half]*alpha + psum;
            #pragma unroll
            for (int j = 0; j < 8; j++){
                accO[j][half*2]   *= alpha;
                accO[j][half*2+1] *= alpha;
            }
        }

        #pragma unroll
        for (int ks = 0; ks < 4; ks++){
            uint32_t aPh[4], aPl[4];
            #pragma unroll
            for (int t = 0; t < 4; t++){
                const int j = 2*ks + (t >> 1);
                const int c0 = (t & 1)*2;
                aPh[t] = split_pack(accS[j][c0], accS[j][c0+1], aPl[t]);
            }
            #pragma unroll
            for (int jj = 0; jj < 4; jj++){
                uint32_t rv = (uint32_t)(ks*16)*AT_STRIDE + (uint32_t)(jj*32) + voff4;
                uint32_t vh4[4], vl4[4];
                ldm_x4_t(V_h + rv, vh4[0], vh4[1], vh4[2], vh4[3]);
                ldm_x4_t(V_l + rv, vl4[0], vl4[1], vl4[2], vl4[3]);
                mma_bf16(accO[2*jj],   aPh, vh4 + 0);
                mma_bf16(accO[2*jj],   aPh, vl4 + 0);
                mma_bf16(accO[2*jj],   aPl, vh4 + 0);
                mma_bf16(accO[2*jj+1], aPh, vh4 + 2);
                mma_bf16(accO[2*jj+1], aPh, vl4 + 2);
                mma_bf16(accO[2*jj+1], aPl, vh4 + 2);
            }
        }
    }

    const float rl0 = 1.0f / l_run[0];
    const float rl1 = 1.0f / l_run[1];
    #pragma unroll
    for (int j = 0; j < 8; j++){
        const int col = h*64 + j*8 + tig*2;
        const size_t o0 = (rowb + row0)*Dc + col;
        const size_t o1 = (rowb + row1)*Dc + col;
        uint32_t lo, hi;
        hi = split_pack(accO[j][0]*rl0, accO[j][1]*rl0, lo);
        *(uint32_t*)(aoh + o0) = hi; *(uint32_t*)(aol + o0) = lo;
        hi = split_pack(accO[j][2]*rl1, accO[j][3]*rl1, lo);
        *(uint32_t*)(aoh + o1) = hi; *(uint32_t*)(aol + o1) = lo;
    }
}

// ---------------------------------------------------------------------------
// Fused weight prep: ALL layers, ALL matrices, one launch.
// 1D grid; per-layer block budget: 4*576 (DxD) + 2*2304 (DxF / FxD) = 6912.
// ---------------------------------------------------------------------------
#define TSB_PER_LAYER 6912

__global__ void __launch_bounds__(256) transpose_split_all(
    const float* __restrict__ Wq, const float* __restrict__ Wk,
    const float* __restrict__ Wv, const float* __restrict__ Wo,
    const float* __restrict__ W1, const float* __restrict__ W2,
    __nv_bfloat16* __restrict__ gh_, __nv_bfloat16* __restrict__ gl_)
{
    const size_t DD = (size_t)Dc*Dc, DF = (size_t)Dc*Fc;
    int l = blockIdx.x / TSB_PER_LAYER;
    int r = blockIdx.x - l*TSB_PER_LAYER;

    const float* src; size_t dst; int K, N, bx, by;
    if (r < 2304){                       // Wq,Wk,Wv,Wo: 768x768, 576 blocks each
        int m = r / 576, t = r - m*576;
        const float* Ws[4] = {Wq, Wk, Wv, Wo};
        src = Ws[m] + (size_t)l*DD; dst = (size_t)l*WT_PER_LAYER + (size_t)m*DD;
        K = Dc; N = Dc; by = t / 24; bx = t - by*24;
    } else if (r < 4608){                // W1: 768x3072
        int t = r - 2304;
        src = W1 + (size_t)l*DF; dst = (size_t)l*WT_PER_LAYER + 4*DD;
        K = Dc; N = Fc; by = t / 96; bx = t - by*96;
    } else {                             // W2: 3072x768
        int t = r - 4608;
        src = W2 + (size_t)l*DF; dst = (size_t)l*WT_PER_LAYER + 4*DD + DF;
        K = Fc; N = Dc; by = t / 24; bx = t - by*24;
    }

    __shared__ float t[32][33];
    const int kb = by*32, nb = bx*32;
    const int x = threadIdx.x & 31, y = (threadIdx.x >> 5) * 4;
    #pragma unroll
    for (int i = 0; i < 4; i++)
        t[y+i][x] = src[(size_t)(kb + y + i)*N + nb + x];
    __syncthreads();
    #pragma unroll
    for (int i = 0; i < 4; i++){
        float v = t[x][y+i];
        __nv_bfloat16 h = __float2bfloat16(v);
        float lo = v - __bfloat162float(h);
        gh_[dst + (size_t)(nb + y + i)*K + kb + x] = h;
        gl_[dst + (size_t)(nb + y + i)*K + kb + x] = __float2bfloat16(lo);
    }
}

// ---------------------------------------------------------------------------
// Activation bf16 split — initial x only
// ---------------------------------------------------------------------------
__global__ void __launch_bounds__(256) split_act(
    const float* __restrict__ in, __nv_bfloat16* __restrict__ oh,
    __nv_bfloat16* __restrict__ ol, int n)
{
    int i = blockIdx.x * 1024 + threadIdx.x * 4;
    if (i >= n) return;
    float4 v = *(const float4*)(in + i);
    float vv[4] = {v.x, v.y, v.z, v.w};
    __nv_bfloat16 h[4], l[4];
    #pragma unroll
    for (int j = 0; j < 4; j++){
        h[j] = __float2bfloat16(vv[j]);
        l[j] = __float2bfloat16(vv[j] - __bfloat162float(h[j]));
    }
    *(uint2*)(oh + i) = *(uint2*)h;
    *(uint2*)(ol + i) = *(uint2*)l;
}

// ---------------------------------------------------------------------------
// out = LayerNorm(res + y) * g + b  -> fp32 out + split bf16
// ---------------------------------------------------------------------------
__global__ void __launch_bounds__(256) add_ln(
    const float* __restrict__ res, const float* __restrict__ y,
    const float* __restrict__ gw, const float* __restrict__ bw,
    float* __restrict__ out,
    __nv_bfloat16* __restrict__ oh, __nv_bfloat16* __restrict__ ol)
{
    const int row = blockIdx.x;
    const float* r  = res + (size_t)row * Dc;
    const float* yy = y   + (size_t)row * Dc;
    float v[3];
    float s = 0.f, s2 = 0.f;
    #pragma unroll
    for (int qq = 0; qq < 3; qq++) {
        int idx = threadIdx.x + qq*256;
        float t = r[idx] + yy[idx];
        v[qq] = t; s += t; s2 += t*t;
    }
    #pragma unroll
    for (int off = 16; off; off >>= 1) {
        s  += __shfl_xor_sync(0xFFFFFFFFu, s,  off);
        s2 += __shfl_xor_sync(0xFFFFFFFFu, s2, off);
    }
    __shared__ float sh[2][8];
    const int w = threadIdx.x >> 5, lane = threadIdx.x & 31;
    if (lane == 0) { sh[0][w] = s; sh[1][w] = s2; }
    __syncthreads();
    float ts = 0.f, ts2 = 0.f;
    #pragma unroll
    for (int i = 0; i < 8; i++) { ts += sh[0][i]; ts2 += sh[1][i]; }
    const float mu  = ts  * (1.0f/768.0f);
    const float var = ts2 * (1.0f/768.0f) - mu*mu;
    const float rstd = rsqrtf(var + 1e-5f);
    #pragma unroll
    for (int qq = 0; qq < 3; qq++) {
        int idx = threadIdx.x + qq*256;
        float o = (v[qq] - mu) * rstd * gw[idx] + bw[idx];
        const size_t off = (size_t)row*Dc + idx;
        out[off] = o;
        __nv_bfloat16 hh = __float2bfloat16(o);
        oh[off] = hh;
        ol[off] = __float2bfloat16(o - __bfloat162float(hh));
    }
}

// ---------------------------------------------------------------------------
// Host launcher
// ---------------------------------------------------------------------------
extern "C" void kernel_launch(void* const* d_in, const int* in_sizes, int n_in,
                              void* d_out, int out_size)
{
    const float* x    = (const float*)d_in[0];
    const float* Wq   = (const float*)d_in[2];
    const float* Wk   = (const float*)d_in[3];
    const float* Wv   = (const float*)d_in[4];
    const float* Wo   = (const float*)d_in[5];
    const float* bo   = (const float*)d_in[6];
    const float* ln1g = (const float*)d_in[7];
    const float* ln1b = (const float*)d_in[8];
    const float* W1   = (const float*)d_in[9];
    const float* b1   = (const float*)d_in[10];
    const float* W2   = (const float*)d_in[11];
    const float* b2   = (const float*)d_in[12];
    const float* ln2g = (const float*)d_in[13];
    const float* ln2b = (const float*)d_in[14];

    float *gx, *gproj, *gh, *gf2;
    __nv_bfloat16 *acth, *actl, *qkvh, *qkvl, *f1h, *f1l, *wh, *wl;
    cudaGetSymbolAddress((void**)&gx,    g_x);
    cudaGetSymbolAddress((void**)&gproj, g_proj);
    cudaGetSymbolAddress((void**)&gh,    g_h);
    cudaGetSymbolAddress((void**)&gf2,   g_f2);
    cudaGetSymbolAddress((void**)&acth,  g_acth);
    cudaGetSymbolAddress((void**)&actl,  g_actl);
    cudaGetSymbolAddress((void**)&qkvh,  g_qkvh);
    cudaGetSymbolAddress((void**)&qkvl,  g_qkvl);
    cudaGetSymbolAddress((void**)&f1h,   g_f1h);
    cudaGetSymbolAddress((void**)&f1l,   g_f1l);
    cudaGetSymbolAddress((void**)&wh,    g_wt_hi);
    cudaGetSymbolAddress((void**)&wl,    g_wt_lo);

    cudaFuncSetAttribute(gemm_tc,        cudaFuncAttributeMaxDynamicSharedMemorySize, GSM_TOTAL);
    cudaFuncSetAttribute(flash_attn_mma, cudaFuncAttributeMaxDynamicSharedMemorySize, FA2_SMEM);

    const size_t DD = (size_t)Dc*Dc, DF = (size_t)Dc*Fc;

    // fused weight prep: one launch for all layers/matrices
    transpose_split_all<<<TSB_PER_LAYER*Lc, 256>>>(Wq, Wk, Wv, Wo, W1, W2, wh, wl);

    cudaMemcpyAsync(gx, x, (size_t)Mc*Dc*sizeof(float), cudaMemcpyDeviceToDevice);
    split_act<<<(Mc*Dc)/1024, 256>>>(gx, acth, actl, Mc*Dc);

    const dim3 gQKV(QKVc/128, Mc/128);  // (18, 64)
    const dim3 gD(Dc/128, Mc/128);      // (6, 64)
    const dim3 gF(Fc/128, Mc/128);      // (24, 64)

    for (int l = 0; l < Lc; l++){
        size_t wb = (size_t)l * WT_PER_LAYER;
        const __nv_bfloat16 *qkvw_h = wh+wb,      *qkvw_l = wl+wb;
        const __nv_bfloat16 *ohw = wh+wb+3*DD,    *olw = wl+wb+3*DD;
        const __nv_bfloat16 *w1h = wh+wb+4*DD,    *w1l = wl+wb+4*DD;
        const __nv_bfloat16 *w2h = wh+wb+4*DD+DF, *w2l = wl+wb+4*DD+DF;

        gemm_tc<<<gQKV, 256, GSM_TOTAL>>>(acth, actl, qkvw_h, qkvw_l, nullptr,
                                          nullptr, qkvh, qkvl, Mc, QKVc, Dc, QKVc, 0);
        flash_attn_mma<<<dim3(Sc/64, Bc*Hc), 128, FA2_SMEM>>>(qkvh, qkvl, acth, actl);
        gemm_tc<<<gD, 256, GSM_TOTAL>>>(acth, actl, ohw, olw, bo + (size_t)l*Dc,
                                        gproj, nullptr, nullptr, Mc, Dc, Dc, Dc, 0);
        add_ln<<<Mc, 256>>>(gx, gproj, ln1g + (size_t)l*Dc, ln1b + (size_t)l*Dc,
                            gh, acth, actl);
        gemm_tc<<<gF, 256, GSM_TOTAL>>>(acth, actl, w1h, w1l, b1 + (size_t)l*Fc,
                                        nullptr, f1h, f1l, Mc, Fc, Dc, Fc, 1);
        gemm_tc<<<gD, 256, GSM_TOTAL>>>(f1h, f1l, w2h, w2l, b2 + (size_t)l*Dc,
                                        gf2, nullptr, nullptr, Mc, Dc, Fc, Dc, 0);
        add_ln<<<Mc, 256>>>(gh, gf2, ln2g + (size_t)l*Dc, ln2b + (size_t)l*Dc,
                            gx, acth, actl);
    }

    cudaMemcpyAsync(d_out, gx, (size_t)Mc*Dc*sizeof(float), cudaMemcpyDeviceToDevice);
}